// round 1
// baseline (speedup 1.0000x reference)
#include <cuda_runtime.h>
#include <cuda_bf16.h>
#include <math.h>

// ---------------- problem constants ----------------
constexpr int NT  = 50000;
constexpr int NC  = 10000;
constexpr int H   = 4;
constexpr int C   = 64;
constexpr int HID = 256;       // H*C
constexpr int E_TT = 400000;
constexpr int E_CT = 200000;
constexpr int FT = 128;
constexpr int FC = 64;

// ---------------- device scratch ----------------
__device__ float g_ht[NT * HID];
__device__ float g_hc[NC * HID];
__device__ float g_p1[NT * HID];
__device__ float g_p2[NT * HID];
__device__ float g_pd[NT * HID];
__device__ float g_ps[NC * HID];
__device__ float g_msg0[NT * HID];
__device__ float g_msg1[NT * HID];
__device__ float g_msg2[NT * HID];
__device__ float g_den[3 * NT * H];
__device__ float g_m[3 * NT * H];
__device__ float g_as[NT * H];
__device__ float g_ad[NT * H];
__device__ float g_x[NT * HID];

// ---------------- SGEMM: C[M,N] = A[M,K] @ B[K,N] (+bias)(+relu) ----------------
// BM=64, BN=64, BK=16, 256 threads, 4x4 micro-tile per thread.
// Requires: K % 16 == 0, N % 64 == 0 (true here: K in {64,128,256}, N=256).
template <bool BIAS, bool RELU>
__global__ void sgemm_kernel(const float* __restrict__ A, const float* __restrict__ B,
                             const float* __restrict__ bias, float* __restrict__ Cout,
                             int M, int N, int K) {
    __shared__ float As[16][68];
    __shared__ float Bs[16][68];

    const int tid = threadIdx.x;
    const int bm = blockIdx.y * 64;
    const int bn = blockIdx.x * 64;
    const int tx = tid & 15;        // 0..15
    const int ty = tid >> 4;        // 0..15

    const int arow = tid >> 2;          // 0..63
    const int acol = (tid & 3) << 2;    // 0,4,8,12
    const int brow = tid >> 4;          // 0..15
    const int bcol = (tid & 15) << 2;   // 0..60

    float acc[4][4];
#pragma unroll
    for (int i = 0; i < 4; i++)
#pragma unroll
        for (int j = 0; j < 4; j++) acc[i][j] = 0.f;

    for (int k0 = 0; k0 < K; k0 += 16) {
        float4 av = make_float4(0.f, 0.f, 0.f, 0.f);
        const int ga = bm + arow;
        if (ga < M)
            av = *reinterpret_cast<const float4*>(A + (size_t)ga * K + k0 + acol);
        As[acol + 0][arow] = av.x;
        As[acol + 1][arow] = av.y;
        As[acol + 2][arow] = av.z;
        As[acol + 3][arow] = av.w;

        float4 bv = *reinterpret_cast<const float4*>(B + (size_t)(k0 + brow) * N + bn + bcol);
        *reinterpret_cast<float4*>(&Bs[brow][bcol]) = bv;

        __syncthreads();

#pragma unroll
        for (int kk = 0; kk < 16; kk++) {
            float a[4], b[4];
#pragma unroll
            for (int i = 0; i < 4; i++) a[i] = As[kk][ty * 4 + i];
#pragma unroll
            for (int j = 0; j < 4; j++) b[j] = Bs[kk][tx * 4 + j];
#pragma unroll
            for (int i = 0; i < 4; i++)
#pragma unroll
                for (int j = 0; j < 4; j++) acc[i][j] = fmaf(a[i], b[j], acc[i][j]);
        }
        __syncthreads();
    }

#pragma unroll
    for (int i = 0; i < 4; i++) {
        const int row = bm + ty * 4 + i;
        if (row >= M) continue;
#pragma unroll
        for (int j = 0; j < 4; j++) {
            const int col = bn + tx * 4 + j;
            float v = acc[i][j];
            if (BIAS) v += bias[col];
            if (RELU) v = fmaxf(v, 0.f);
            Cout[(size_t)row * N + col] = v;
        }
    }
}

// ---------------- per-(node,head) attention logit: out[n,h] = dot(p[n,h,:], att[h,:]) ----
__global__ void alpha_kernel(const float* __restrict__ p, const float* __restrict__ att,
                             float* __restrict__ out, int N) {
    const int gw = (blockIdx.x * blockDim.x + threadIdx.x) >> 5;
    const int lane = threadIdx.x & 31;
    if (gw >= N * H) return;
    const int n = gw >> 2;
    const int h = gw & 3;
    const float* pr = p + (size_t)n * HID + h * 64;
    const float* at = att + h * 64;
    float s = pr[lane] * at[lane] + pr[lane + 32] * at[lane + 32];
#pragma unroll
    for (int o = 16; o > 0; o >>= 1) s += __shfl_down_sync(0xffffffffu, s, o);
    if (lane == 0) out[gw] = s;
}

__device__ __forceinline__ void atomicMaxFloat(float* addr, float value) {
    if (value >= 0.f)
        atomicMax(reinterpret_cast<int*>(addr), __float_as_int(value));
    else
        atomicMin(reinterpret_cast<unsigned int*>(addr), __float_as_uint(value));
}

__global__ void fill_neg_inf(float* __restrict__ p, int n) {
    const int i = blockIdx.x * blockDim.x + threadIdx.x;
    if (i < n) p[i] = __int_as_float(0xff800000);
}

// ---------------- edge pass 1: segment max of leaky-relu'd logits ----------------
__global__ void edge_max_kernel(const int* __restrict__ src, const int* __restrict__ dst,
                                int E, int nLoops,
                                const float* __restrict__ as_, const float* __restrict__ ad_,
                                float* __restrict__ m) {
    const int e = blockIdx.x * blockDim.x + threadIdx.x;
    const int total = E + nLoops;
    if (e >= total) return;
    int s, d;
    if (e < E) { s = src[e]; d = dst[e]; }
    else { s = e - E; d = s; }
    const float4 a4 = reinterpret_cast<const float4*>(as_)[s];
    const float4 b4 = reinterpret_cast<const float4*>(ad_)[d];
    float a;
    a = a4.x + b4.x; a = a > 0.f ? a : 0.2f * a; atomicMaxFloat(&m[d * 4 + 0], a);
    a = a4.y + b4.y; a = a > 0.f ? a : 0.2f * a; atomicMaxFloat(&m[d * 4 + 1], a);
    a = a4.z + b4.z; a = a > 0.f ? a : 0.2f * a; atomicMaxFloat(&m[d * 4 + 2], a);
    a = a4.w + b4.w; a = a > 0.f ? a : 0.2f * a; atomicMaxFloat(&m[d * 4 + 3], a);
}

// ---------------- edge pass 2: ex = exp(a - m[dst]); den += ex; msg += ex * xs[src] ----
// one warp per edge
__global__ void edge_sum_kernel(const int* __restrict__ src, const int* __restrict__ dst,
                                int E, int nLoops,
                                const float* __restrict__ as_, const float* __restrict__ ad_,
                                const float* __restrict__ m,
                                const float* __restrict__ xs,
                                float* __restrict__ den, float* __restrict__ msg) {
    const int gw = (blockIdx.x * blockDim.x + threadIdx.x) >> 5;
    const int lane = threadIdx.x & 31;
    const int total = E + nLoops;
    if (gw >= total) return;
    int s, d;
    if (gw < E) { s = src[gw]; d = dst[gw]; }
    else { s = gw - E; d = s; }

    float ex = 0.f;
    if (lane < 4) {
        float a = as_[s * 4 + lane] + ad_[d * 4 + lane];
        a = a > 0.f ? a : 0.2f * a;
        ex = expf(a - m[d * 4 + lane]);
        atomicAdd(&den[d * 4 + lane], ex);
    }
    const float e0 = __shfl_sync(0xffffffffu, ex, 0);
    const float e1 = __shfl_sync(0xffffffffu, ex, 1);
    const float e2 = __shfl_sync(0xffffffffu, ex, 2);
    const float e3 = __shfl_sync(0xffffffffu, ex, 3);

    const float* xr = xs + (size_t)s * HID;
    float* mr = msg + (size_t)d * HID;
#pragma unroll
    for (int i = 0; i < 8; i++) {
        const int k = lane + i * 32;
        const float w = (i < 2) ? e0 : (i < 4) ? e1 : (i < 6) ? e2 : e3;
        atomicAdd(&mr[k], w * xr[k]);
    }
}

// ---------------- combine: x = relu(0.25*o1 + 0.25*o2 + 0.5*o3 + ht) ----------------
__global__ void combine_kernel(const float* __restrict__ msg0, const float* __restrict__ msg1,
                               const float* __restrict__ msg2, const float* __restrict__ den,
                               const float* __restrict__ b1, const float* __restrict__ b2,
                               const float* __restrict__ b3,
                               const float* __restrict__ ht, float* __restrict__ xout) {
    const int idx = blockIdx.x * blockDim.x + threadIdx.x;
    if (idx >= NT * HID) return;
    const int n = idx >> 8;
    const int k = idx & 255;
    const int h = k >> 6;
    const float d0 = fmaxf(den[0 * NT * H + n * 4 + h], 1e-16f);
    const float d1 = fmaxf(den[1 * NT * H + n * 4 + h], 1e-16f);
    const float d2 = fmaxf(den[2 * NT * H + n * 4 + h], 1e-16f);
    const float o1 = msg0[idx] / d0 + b1[k];
    const float o2 = msg1[idx] / d1 + b2[k];
    const float o3 = msg2[idx] / d2 + b3[k];
    float x = 0.25f * (o1 + o2) + 0.5f * o3;
    x += ht[idx];
    xout[idx] = fmaxf(x, 0.f);
}

// ---------------- launch ----------------
extern "C" void kernel_launch(void* const* d_in, const int* in_sizes, int n_in,
                              void* d_out, int out_size) {
    const float* x_target = (const float*)d_in[0];
    const float* x_context = (const float*)d_in[1];
    const int*   ei_tt     = (const int*)d_in[2];      // [2, E_TT]
    const int*   ei_ct_src = (const int*)d_in[3];
    const int*   ei_ct_dst = (const int*)d_in[4];
    const float* Wt = (const float*)d_in[5];
    const float* bt = (const float*)d_in[6];
    const float* Wc = (const float*)d_in[7];
    const float* bc = (const float*)d_in[8];
    const float* W_s2d  = (const float*)d_in[9];
    const float* as_s2d = (const float*)d_in[10];
    const float* ad_s2d = (const float*)d_in[11];
    const float* b_s2d  = (const float*)d_in[12];
    const float* W_d2s  = (const float*)d_in[13];
    const float* as_d2s = (const float*)d_in[14];
    const float* ad_d2s = (const float*)d_in[15];
    const float* b_d2s  = (const float*)d_in[16];
    const float* W_ct_src = (const float*)d_in[17];
    const float* W_ct_dst = (const float*)d_in[18];
    const float* as_ct  = (const float*)d_in[19];
    const float* ad_ct  = (const float*)d_in[20];
    const float* b_ct   = (const float*)d_in[21];
    const float* W_out  = (const float*)d_in[22];
    const float* b_out  = (const float*)d_in[23];

    float *ht, *hc, *p1, *p2, *pd, *ps, *msg0, *msg1, *msg2, *den, *m, *as_, *ad_, *xb;
    cudaGetSymbolAddress((void**)&ht,   g_ht);
    cudaGetSymbolAddress((void**)&hc,   g_hc);
    cudaGetSymbolAddress((void**)&p1,   g_p1);
    cudaGetSymbolAddress((void**)&p2,   g_p2);
    cudaGetSymbolAddress((void**)&pd,   g_pd);
    cudaGetSymbolAddress((void**)&ps,   g_ps);
    cudaGetSymbolAddress((void**)&msg0, g_msg0);
    cudaGetSymbolAddress((void**)&msg1, g_msg1);
    cudaGetSymbolAddress((void**)&msg2, g_msg2);
    cudaGetSymbolAddress((void**)&den,  g_den);
    cudaGetSymbolAddress((void**)&m,    g_m);
    cudaGetSymbolAddress((void**)&as_,  g_as);
    cudaGetSymbolAddress((void**)&ad_,  g_ad);
    cudaGetSymbolAddress((void**)&xb,   g_x);

    // zero accumulators, fill segment-max with -inf
    cudaMemsetAsync(msg0, 0, sizeof(float) * NT * HID, 0);
    cudaMemsetAsync(msg1, 0, sizeof(float) * NT * HID, 0);
    cudaMemsetAsync(msg2, 0, sizeof(float) * NT * HID, 0);
    cudaMemsetAsync(den,  0, sizeof(float) * 3 * NT * H, 0);
    {
        const int n = 3 * NT * H;
        fill_neg_inf<<<(n + 255) / 256, 256>>>(m, n);
    }

    const dim3 blk(256);
    const dim3 g_ht_grid(HID / 64, (NT + 63) / 64);
    const dim3 g_hc_grid(HID / 64, (NC + 63) / 64);

    // pretransform + relu
    sgemm_kernel<true, true><<<g_ht_grid, blk>>>(x_target, Wt, bt, ht, NT, HID, FT);
    sgemm_kernel<true, true><<<g_hc_grid, blk>>>(x_context, Wc, bc, hc, NC, HID, FC);

    // projections
    sgemm_kernel<false, false><<<g_ht_grid, blk>>>(ht, W_s2d,  nullptr, p1, NT, HID, HID);
    sgemm_kernel<false, false><<<g_ht_grid, blk>>>(ht, W_d2s,  nullptr, p2, NT, HID, HID);
    sgemm_kernel<false, false><<<g_ht_grid, blk>>>(ht, W_ct_dst, nullptr, pd, NT, HID, HID);
    sgemm_kernel<false, false><<<g_hc_grid, blk>>>(hc, W_ct_src, nullptr, ps, NC, HID, HID);

    const int* tt_src = ei_tt;
    const int* tt_dst = ei_tt + E_TT;

    const int aw_nt = NT * H * 32;                  // alpha threads for NT nodes
    const int aw_nc = NC * H * 32;
    const int ett_total = E_TT + NT;                // with self loops
    const int ett_warp_threads = ett_total * 32;
    const int ect_warp_threads = E_CT * 32;

    // ---- graph 0: s2d (src->dst), xs = xd = p1 ----
    alpha_kernel<<<(aw_nt + 255) / 256, 256>>>(p1, as_s2d, as_, NT);
    alpha_kernel<<<(aw_nt + 255) / 256, 256>>>(p1, ad_s2d, ad_, NT);
    edge_max_kernel<<<(ett_total + 255) / 256, 256>>>(tt_src, tt_dst, E_TT, NT, as_, ad_, m);
    edge_sum_kernel<<<(ett_warp_threads + 255) / 256, 256>>>(
        tt_src, tt_dst, E_TT, NT, as_, ad_, m, p1, den, msg0);

    // ---- graph 1: d2s (reversed edges), xs = xd = p2 ----
    alpha_kernel<<<(aw_nt + 255) / 256, 256>>>(p2, as_d2s, as_, NT);
    alpha_kernel<<<(aw_nt + 255) / 256, 256>>>(p2, ad_d2s, ad_, NT);
    edge_max_kernel<<<(ett_total + 255) / 256, 256>>>(tt_dst, tt_src, E_TT, NT, as_, ad_,
                                                      m + NT * H);
    edge_sum_kernel<<<(ett_warp_threads + 255) / 256, 256>>>(
        tt_dst, tt_src, E_TT, NT, as_, ad_, m + NT * H, p2, den + NT * H, msg1);

    // ---- graph 2: context -> target bipartite, xs = ps, xd = pd, no self loops ----
    alpha_kernel<<<(aw_nc + 255) / 256, 256>>>(ps, as_ct, as_, NC);
    alpha_kernel<<<(aw_nt + 255) / 256, 256>>>(pd, ad_ct, ad_, NT);
    edge_max_kernel<<<(E_CT + 255) / 256, 256>>>(ei_ct_src, ei_ct_dst, E_CT, 0, as_, ad_,
                                                 m + 2 * NT * H);
    edge_sum_kernel<<<(ect_warp_threads + 255) / 256, 256>>>(
        ei_ct_src, ei_ct_dst, E_CT, 0, as_, ad_, m + 2 * NT * H, ps, den + 2 * NT * H, msg2);

    // ---- combine + skip + relu ----
    combine_kernel<<<(NT * HID + 255) / 256, 256>>>(msg0, msg1, msg2, den,
                                                    b_s2d, b_d2s, b_ct, ht, xb);

    // ---- final linear ----
    sgemm_kernel<true, false><<<g_ht_grid, blk>>>(xb, W_out, b_out, (float*)d_out,
                                                  NT, HID, HID);
}

// round 2
// speedup vs baseline: 1.1464x; 1.1464x over previous
#include <cuda_runtime.h>
#include <cuda_bf16.h>
#include <math.h>

typedef unsigned long long ull;

// ---------------- problem constants ----------------
constexpr int NT  = 50000;
constexpr int NC  = 10000;
constexpr int H   = 4;
constexpr int C   = 64;
constexpr int HID = 256;       // H*C
constexpr int E_TT = 400000;
constexpr int E_CT = 200000;
constexpr int FT = 128;
constexpr int FC = 64;

// ---------------- device scratch ----------------
__device__ float g_ht[NT * HID];
__device__ float g_hc[NC * HID];
__device__ float g_p1[NT * HID];
__device__ float g_p2[NT * HID];
__device__ float g_pd[NT * HID];
__device__ float g_ps[NC * HID];
__device__ float g_msg0[NT * HID];
__device__ float g_msg1[NT * HID];
__device__ float g_msg2[NT * HID];
__device__ float g_den[3 * NT * H];
__device__ float g_m[3 * NT * H];
__device__ float g_as[NT * H];
__device__ float g_ad[NT * H];
__device__ float g_x[NT * HID];

// ---------------- packed f32x2 helpers ----------------
__device__ __forceinline__ ull dup2(float x) {
    ull r;
    asm("mov.b64 %0, {%1, %1};" : "=l"(r) : "f"(x));
    return r;
}
__device__ __forceinline__ void ffma2(ull& d, ull a, ull b) {
    asm("fma.rn.f32x2 %0, %1, %2, %0;" : "+l"(d) : "l"(a), "l"(b));
}
__device__ __forceinline__ float2 unpack2(ull v) {
    float2 r;
    asm("mov.b64 {%0, %1}, %2;" : "=f"(r.x), "=f"(r.y) : "l"(v));
    return r;   // .x = low half = lower shared address = even row
}

// ---------------- SGEMM via FFMA2: C[M,N] = A[M,K] @ B[K,N] (+bias)(+relu) ----
// BM=128, BN=64, BK=16, 256 threads, 8(M)x4(N) micro-tile held as 4x4 f32x2.
// Requires: K % 16 == 0, N % 64 == 0.
template <bool BIAS, bool RELU>
__global__ void __launch_bounds__(256) sgemm2_kernel(
        const float* __restrict__ A, const float* __restrict__ B,
        const float* __restrict__ bias, float* __restrict__ Cout,
        int M, int N, int K) {
    __shared__ float As[16][132];   // [k][row]  (transposed A tile), row pad->132
    __shared__ float Bs[16][68];    // [k][col]

    const int tid = threadIdx.x;
    const int bm = blockIdx.y * 128;
    const int bn = blockIdx.x * 64;
    const int tx = tid & 15;        // col group: 4 cols
    const int ty = tid >> 4;        // row group: 8 rows

    ull acc[4][4];                  // [row-pair][col]
#pragma unroll
    for (int i = 0; i < 4; i++)
#pragma unroll
        for (int j = 0; j < 4; j++) acc[i][j] = 0ull;

    const int brow = tid >> 4;          // 0..15
    const int bcol = (tid & 15) << 2;   // 0..60

    for (int k0 = 0; k0 < K; k0 += 16) {
        // load A tile: 128 rows x 16 k  -> 512 float4, 2 per thread, transposed
#pragma unroll
        for (int li = 0; li < 2; li++) {
            const int idx = tid + li * 256;     // 0..511
            const int row = idx >> 2;           // 0..127
            const int kg  = (idx & 3) << 2;     // 0,4,8,12
            float4 av = make_float4(0.f, 0.f, 0.f, 0.f);
            const int ga = bm + row;
            if (ga < M)
                av = *reinterpret_cast<const float4*>(A + (size_t)ga * K + k0 + kg);
            As[kg + 0][row] = av.x;
            As[kg + 1][row] = av.y;
            As[kg + 2][row] = av.z;
            As[kg + 3][row] = av.w;
        }
        // load B tile: 16 x 64
        {
            float4 bv = *reinterpret_cast<const float4*>(B + (size_t)(k0 + brow) * N + bn + bcol);
            *reinterpret_cast<float4*>(&Bs[brow][bcol]) = bv;
        }
        __syncthreads();

#pragma unroll
        for (int kk = 0; kk < 16; kk++) {
            // 4 row-pairs of A, loaded directly as 64-bit values (LDS.64)
            ull ap[4];
#pragma unroll
            for (int ip = 0; ip < 4; ip++)
                ap[ip] = *reinterpret_cast<const ull*>(&As[kk][ty * 8 + ip * 2]);
            // 4 B values, duplicated into both packed halves
            const float4 bv4 = *reinterpret_cast<const float4*>(&Bs[kk][tx * 4]);
            ull bd[4];
            bd[0] = dup2(bv4.x);
            bd[1] = dup2(bv4.y);
            bd[2] = dup2(bv4.z);
            bd[3] = dup2(bv4.w);
#pragma unroll
            for (int ip = 0; ip < 4; ip++)
#pragma unroll
                for (int j = 0; j < 4; j++)
                    ffma2(acc[ip][j], ap[ip], bd[j]);
        }
        __syncthreads();
    }

    // epilogue: unpack row pairs, store float4 per row
#pragma unroll
    for (int ip = 0; ip < 4; ip++) {
        float4 v0, v1;          // even row, odd row
        float2 u;
        u = unpack2(acc[ip][0]); v0.x = u.x; v1.x = u.y;
        u = unpack2(acc[ip][1]); v0.y = u.x; v1.y = u.y;
        u = unpack2(acc[ip][2]); v0.z = u.x; v1.z = u.y;
        u = unpack2(acc[ip][3]); v0.w = u.x; v1.w = u.y;
        const int col = bn + tx * 4;
        if (BIAS) {
            const float4 bb = *reinterpret_cast<const float4*>(bias + col);
            v0.x += bb.x; v0.y += bb.y; v0.z += bb.z; v0.w += bb.w;
            v1.x += bb.x; v1.y += bb.y; v1.z += bb.z; v1.w += bb.w;
        }
        if (RELU) {
            v0.x = fmaxf(v0.x, 0.f); v0.y = fmaxf(v0.y, 0.f);
            v0.z = fmaxf(v0.z, 0.f); v0.w = fmaxf(v0.w, 0.f);
            v1.x = fmaxf(v1.x, 0.f); v1.y = fmaxf(v1.y, 0.f);
            v1.z = fmaxf(v1.z, 0.f); v1.w = fmaxf(v1.w, 0.f);
        }
        const int r0 = bm + ty * 8 + ip * 2;
        if (r0 < M)
            *reinterpret_cast<float4*>(Cout + (size_t)r0 * N + col) = v0;
        if (r0 + 1 < M)
            *reinterpret_cast<float4*>(Cout + (size_t)(r0 + 1) * N + col) = v1;
    }
}

// ---------------- per-(node,head) attention logit ----------------
__global__ void alpha_kernel(const float* __restrict__ p, const float* __restrict__ att,
                             float* __restrict__ out, int N) {
    const int gw = (blockIdx.x * blockDim.x + threadIdx.x) >> 5;
    const int lane = threadIdx.x & 31;
    if (gw >= N * H) return;
    const int n = gw >> 2;
    const int h = gw & 3;
    const float* pr = p + (size_t)n * HID + h * 64;
    const float* at = att + h * 64;
    float s = pr[lane] * at[lane] + pr[lane + 32] * at[lane + 32];
#pragma unroll
    for (int o = 16; o > 0; o >>= 1) s += __shfl_down_sync(0xffffffffu, s, o);
    if (lane == 0) out[gw] = s;
}

__device__ __forceinline__ void atomicMaxFloat(float* addr, float value) {
    if (value >= 0.f)
        atomicMax(reinterpret_cast<int*>(addr), __float_as_int(value));
    else
        atomicMin(reinterpret_cast<unsigned int*>(addr), __float_as_uint(value));
}

__global__ void fill_neg_inf(float* __restrict__ p, int n) {
    const int i = blockIdx.x * blockDim.x + threadIdx.x;
    if (i < n) p[i] = __int_as_float(0xff800000);
}

// ---------------- edge pass 1: segment max ----------------
__global__ void edge_max_kernel(const int* __restrict__ src, const int* __restrict__ dst,
                                int E, int nLoops,
                                const float* __restrict__ as_, const float* __restrict__ ad_,
                                float* __restrict__ m) {
    const int e = blockIdx.x * blockDim.x + threadIdx.x;
    const int total = E + nLoops;
    if (e >= total) return;
    int s, d;
    if (e < E) { s = src[e]; d = dst[e]; }
    else { s = e - E; d = s; }
    const float4 a4 = reinterpret_cast<const float4*>(as_)[s];
    const float4 b4 = reinterpret_cast<const float4*>(ad_)[d];
    float a;
    a = a4.x + b4.x; a = a > 0.f ? a : 0.2f * a; atomicMaxFloat(&m[d * 4 + 0], a);
    a = a4.y + b4.y; a = a > 0.f ? a : 0.2f * a; atomicMaxFloat(&m[d * 4 + 1], a);
    a = a4.z + b4.z; a = a > 0.f ? a : 0.2f * a; atomicMaxFloat(&m[d * 4 + 2], a);
    a = a4.w + b4.w; a = a > 0.f ? a : 0.2f * a; atomicMaxFloat(&m[d * 4 + 3], a);
}

// ---------------- edge pass 2: exp + weighted scatter (one warp/edge) ----------
__global__ void edge_sum_kernel(const int* __restrict__ src, const int* __restrict__ dst,
                                int E, int nLoops,
                                const float* __restrict__ as_, const float* __restrict__ ad_,
                                const float* __restrict__ m,
                                const float* __restrict__ xs,
                                float* __restrict__ den, float* __restrict__ msg) {
    const int gw = (blockIdx.x * blockDim.x + threadIdx.x) >> 5;
    const int lane = threadIdx.x & 31;
    const int total = E + nLoops;
    if (gw >= total) return;
    int s, d;
    if (gw < E) { s = src[gw]; d = dst[gw]; }
    else { s = gw - E; d = s; }

    float ex = 0.f;
    if (lane < 4) {
        float a = as_[s * 4 + lane] + ad_[d * 4 + lane];
        a = a > 0.f ? a : 0.2f * a;
        ex = expf(a - m[d * 4 + lane]);
        atomicAdd(&den[d * 4 + lane], ex);
    }
    const float e0 = __shfl_sync(0xffffffffu, ex, 0);
    const float e1 = __shfl_sync(0xffffffffu, ex, 1);
    const float e2 = __shfl_sync(0xffffffffu, ex, 2);
    const float e3 = __shfl_sync(0xffffffffu, ex, 3);

    const float* xr = xs + (size_t)s * HID;
    float* mr = msg + (size_t)d * HID;
#pragma unroll
    for (int i = 0; i < 8; i++) {
        const int k = lane + i * 32;
        const float w = (i < 2) ? e0 : (i < 4) ? e1 : (i < 6) ? e2 : e3;
        atomicAdd(&mr[k], w * xr[k]);
    }
}

// ---------------- combine: x = relu(0.25*o1 + 0.25*o2 + 0.5*o3 + ht) ----------
__global__ void combine_kernel(const float* __restrict__ msg0, const float* __restrict__ msg1,
                               const float* __restrict__ msg2, const float* __restrict__ den,
                               const float* __restrict__ b1, const float* __restrict__ b2,
                               const float* __restrict__ b3,
                               const float* __restrict__ ht, float* __restrict__ xout) {
    const int idx = blockIdx.x * blockDim.x + threadIdx.x;
    if (idx >= NT * HID) return;
    const int n = idx >> 8;
    const int k = idx & 255;
    const int h = k >> 6;
    const float d0 = fmaxf(den[0 * NT * H + n * 4 + h], 1e-16f);
    const float d1 = fmaxf(den[1 * NT * H + n * 4 + h], 1e-16f);
    const float d2 = fmaxf(den[2 * NT * H + n * 4 + h], 1e-16f);
    const float o1 = msg0[idx] / d0 + b1[k];
    const float o2 = msg1[idx] / d1 + b2[k];
    const float o3 = msg2[idx] / d2 + b3[k];
    float x = 0.25f * (o1 + o2) + 0.5f * o3;
    x += ht[idx];
    xout[idx] = fmaxf(x, 0.f);
}

// ---------------- launch ----------------
extern "C" void kernel_launch(void* const* d_in, const int* in_sizes, int n_in,
                              void* d_out, int out_size) {
    const float* x_target = (const float*)d_in[0];
    const float* x_context = (const float*)d_in[1];
    const int*   ei_tt     = (const int*)d_in[2];      // [2, E_TT]
    const int*   ei_ct_src = (const int*)d_in[3];
    const int*   ei_ct_dst = (const int*)d_in[4];
    const float* Wt = (const float*)d_in[5];
    const float* bt = (const float*)d_in[6];
    const float* Wc = (const float*)d_in[7];
    const float* bc = (const float*)d_in[8];
    const float* W_s2d  = (const float*)d_in[9];
    const float* as_s2d = (const float*)d_in[10];
    const float* ad_s2d = (const float*)d_in[11];
    const float* b_s2d  = (const float*)d_in[12];
    const float* W_d2s  = (const float*)d_in[13];
    const float* as_d2s = (const float*)d_in[14];
    const float* ad_d2s = (const float*)d_in[15];
    const float* b_d2s  = (const float*)d_in[16];
    const float* W_ct_src = (const float*)d_in[17];
    const float* W_ct_dst = (const float*)d_in[18];
    const float* as_ct  = (const float*)d_in[19];
    const float* ad_ct  = (const float*)d_in[20];
    const float* b_ct   = (const float*)d_in[21];
    const float* W_out  = (const float*)d_in[22];
    const float* b_out  = (const float*)d_in[23];

    float *ht, *hc, *p1, *p2, *pd, *ps, *msg0, *msg1, *msg2, *den, *m, *as_, *ad_, *xb;
    cudaGetSymbolAddress((void**)&ht,   g_ht);
    cudaGetSymbolAddress((void**)&hc,   g_hc);
    cudaGetSymbolAddress((void**)&p1,   g_p1);
    cudaGetSymbolAddress((void**)&p2,   g_p2);
    cudaGetSymbolAddress((void**)&pd,   g_pd);
    cudaGetSymbolAddress((void**)&ps,   g_ps);
    cudaGetSymbolAddress((void**)&msg0, g_msg0);
    cudaGetSymbolAddress((void**)&msg1, g_msg1);
    cudaGetSymbolAddress((void**)&msg2, g_msg2);
    cudaGetSymbolAddress((void**)&den,  g_den);
    cudaGetSymbolAddress((void**)&m,    g_m);
    cudaGetSymbolAddress((void**)&as_,  g_as);
    cudaGetSymbolAddress((void**)&ad_,  g_ad);
    cudaGetSymbolAddress((void**)&xb,   g_x);

    // zero accumulators, fill segment-max with -inf
    cudaMemsetAsync(msg0, 0, sizeof(float) * NT * HID, 0);
    cudaMemsetAsync(msg1, 0, sizeof(float) * NT * HID, 0);
    cudaMemsetAsync(msg2, 0, sizeof(float) * NT * HID, 0);
    cudaMemsetAsync(den,  0, sizeof(float) * 3 * NT * H, 0);
    {
        const int n = 3 * NT * H;
        fill_neg_inf<<<(n + 255) / 256, 256>>>(m, n);
    }

    const dim3 blk(256);
    const dim3 g_ht_grid(HID / 64, (NT + 127) / 128);
    const dim3 g_hc_grid(HID / 64, (NC + 127) / 128);

    // pretransform + relu
    sgemm2_kernel<true, true><<<g_ht_grid, blk>>>(x_target, Wt, bt, ht, NT, HID, FT);
    sgemm2_kernel<true, true><<<g_hc_grid, blk>>>(x_context, Wc, bc, hc, NC, HID, FC);

    // projections
    sgemm2_kernel<false, false><<<g_ht_grid, blk>>>(ht, W_s2d,  nullptr, p1, NT, HID, HID);
    sgemm2_kernel<false, false><<<g_ht_grid, blk>>>(ht, W_d2s,  nullptr, p2, NT, HID, HID);
    sgemm2_kernel<false, false><<<g_ht_grid, blk>>>(ht, W_ct_dst, nullptr, pd, NT, HID, HID);
    sgemm2_kernel<false, false><<<g_hc_grid, blk>>>(hc, W_ct_src, nullptr, ps, NC, HID, HID);

    const int* tt_src = ei_tt;
    const int* tt_dst = ei_tt + E_TT;

    const int aw_nt = NT * H * 32;
    const int aw_nc = NC * H * 32;
    const int ett_total = E_TT + NT;                // with self loops
    const int ett_warp_threads = ett_total * 32;
    const int ect_warp_threads = E_CT * 32;

    // ---- graph 0: s2d (src->dst), xs = xd = p1 ----
    alpha_kernel<<<(aw_nt + 255) / 256, 256>>>(p1, as_s2d, as_, NT);
    alpha_kernel<<<(aw_nt + 255) / 256, 256>>>(p1, ad_s2d, ad_, NT);
    edge_max_kernel<<<(ett_total + 255) / 256, 256>>>(tt_src, tt_dst, E_TT, NT, as_, ad_, m);
    edge_sum_kernel<<<(ett_warp_threads + 255) / 256, 256>>>(
        tt_src, tt_dst, E_TT, NT, as_, ad_, m, p1, den, msg0);

    // ---- graph 1: d2s (reversed edges), xs = xd = p2 ----
    alpha_kernel<<<(aw_nt + 255) / 256, 256>>>(p2, as_d2s, as_, NT);
    alpha_kernel<<<(aw_nt + 255) / 256, 256>>>(p2, ad_d2s, ad_, NT);
    edge_max_kernel<<<(ett_total + 255) / 256, 256>>>(tt_dst, tt_src, E_TT, NT, as_, ad_,
                                                      m + NT * H);
    edge_sum_kernel<<<(ett_warp_threads + 255) / 256, 256>>>(
        tt_dst, tt_src, E_TT, NT, as_, ad_, m + NT * H, p2, den + NT * H, msg1);

    // ---- graph 2: context -> target bipartite ----
    alpha_kernel<<<(aw_nc + 255) / 256, 256>>>(ps, as_ct, as_, NC);
    alpha_kernel<<<(aw_nt + 255) / 256, 256>>>(pd, ad_ct, ad_, NT);
    edge_max_kernel<<<(E_CT + 255) / 256, 256>>>(ei_ct_src, ei_ct_dst, E_CT, 0, as_, ad_,
                                                 m + 2 * NT * H);
    edge_sum_kernel<<<(ect_warp_threads + 255) / 256, 256>>>(
        ei_ct_src, ei_ct_dst, E_CT, 0, as_, ad_, m + 2 * NT * H, ps, den + 2 * NT * H, msg2);

    // ---- combine + skip + relu ----
    combine_kernel<<<(NT * HID + 255) / 256, 256>>>(msg0, msg1, msg2, den,
                                                    b_s2d, b_d2s, b_ct, ht, xb);

    // ---- final linear ----
    sgemm2_kernel<true, false><<<g_ht_grid, blk>>>(xb, W_out, b_out, (float*)d_out,
                                                   NT, HID, HID);
}

// round 3
// speedup vs baseline: 1.2697x; 1.1076x over previous
#include <cuda_runtime.h>
#include <cuda_bf16.h>
#include <math.h>
#include <stdint.h>

typedef unsigned long long ull;

// ---------------- problem constants ----------------
constexpr int NT  = 50000;
constexpr int NC  = 10000;
constexpr int H   = 4;
constexpr int C   = 64;
constexpr int HID = 256;       // H*C
constexpr int E_TT = 400000;
constexpr int E_CT = 200000;
constexpr int FT = 128;
constexpr int FC = 64;

// ---------------- device scratch ----------------
__device__ float g_ht[NT * HID];
__device__ float g_hc[NC * HID];
__device__ float g_p1[NT * HID];
__device__ float g_p2[NT * HID];
__device__ float g_pd[NT * HID];
__device__ float g_ps[NC * HID];
__device__ float g_msg0[NT * HID];
__device__ float g_msg1[NT * HID];
__device__ float g_msg2[NT * HID];
__device__ float g_den[3 * NT * H];
__device__ float g_m[3 * NT * H];
__device__ float g_as[NT * H];
__device__ float g_ad[NT * H];
__device__ float g_x[NT * HID];

// ================= bf16 double-split tensor-core GEMM =================
// C[M,N] = A[M,K] @ B[K,N] (+bias)(+relu), fp32 in/out.
// A = Ahi + Alo (bf16), B = Bhi + Blo (bf16); C ~= AhiBhi + AhiBlo + AloBhi.
// CTA tile 128x128, BK=32, 256 threads (8 warps, 2x4), warp tile 64x32.
// Requires K % 32 == 0, N % 128 == 0 (here K in {64,128,256}, N = 256).

constexpr int SA = 40;   // A smem row stride (bf16 units), conflict-free frag reads
constexpr int SB = 42;   // B smem row stride (bf16 units), conflict-free frag reads

__device__ __forceinline__ uint32_t pk(__nv_bfloat16 a, __nv_bfloat16 b) {
    return (uint32_t)__bfloat16_as_ushort(a) | ((uint32_t)__bfloat16_as_ushort(b) << 16);
}

__device__ __forceinline__ void mma16816(float* c, const uint32_t* a, const uint32_t* b) {
    asm volatile(
        "mma.sync.aligned.m16n8k16.row.col.f32.bf16.bf16.f32 "
        "{%0,%1,%2,%3}, {%4,%5,%6,%7}, {%8,%9}, {%0,%1,%2,%3};"
        : "+f"(c[0]), "+f"(c[1]), "+f"(c[2]), "+f"(c[3])
        : "r"(a[0]), "r"(a[1]), "r"(a[2]), "r"(a[3]), "r"(b[0]), "r"(b[1]));
}

template <bool BIAS, bool RELU>
__global__ void __launch_bounds__(256) mma_gemm(
        const float* __restrict__ A, const float* __restrict__ B,
        const float* __restrict__ bias, float* __restrict__ Cout,
        int M, int N, int K) {
    __shared__ __nv_bfloat16 sAhi[128 * SA];
    __shared__ __nv_bfloat16 sAlo[128 * SA];
    __shared__ __nv_bfloat16 sBhi[128 * SB];
    __shared__ __nv_bfloat16 sBlo[128 * SB];

    const int tid = threadIdx.x;
    const int bm = blockIdx.y * 128;
    const int bn = blockIdx.x * 128;
    const int wid = tid >> 5;
    const int lane = tid & 31;
    const int wm = wid >> 2;          // 0..1 -> 64 rows
    const int wn = wid & 3;           // 0..3 -> 32 cols
    const int g = lane >> 2;          // 0..7
    const int t = lane & 3;           // 0..3

    float acc[4][4][4];
#pragma unroll
    for (int mi = 0; mi < 4; mi++)
#pragma unroll
        for (int ni = 0; ni < 4; ni++)
#pragma unroll
            for (int r = 0; r < 4; r++) acc[mi][ni][r] = 0.f;

    for (int k0 = 0; k0 < K; k0 += 32) {
        // ---- fill A tile: 128 rows x 32 k, split hi/lo ----
#pragma unroll
        for (int li = 0; li < 4; li++) {
            const int idx = tid + li * 256;        // 0..1023
            const int row = idx >> 3;              // 0..127
            const int kg = (idx & 7) << 2;         // 0,4,..,28
            float4 av = make_float4(0.f, 0.f, 0.f, 0.f);
            const int grow = bm + row;
            if (grow < M)
                av = *reinterpret_cast<const float4*>(A + (size_t)grow * K + k0 + kg);
            __nv_bfloat16 h0 = __float2bfloat16(av.x);
            __nv_bfloat16 h1 = __float2bfloat16(av.y);
            __nv_bfloat16 h2 = __float2bfloat16(av.z);
            __nv_bfloat16 h3 = __float2bfloat16(av.w);
            __nv_bfloat16 l0 = __float2bfloat16(av.x - __bfloat162float(h0));
            __nv_bfloat16 l1 = __float2bfloat16(av.y - __bfloat162float(h1));
            __nv_bfloat16 l2 = __float2bfloat16(av.z - __bfloat162float(h2));
            __nv_bfloat16 l3 = __float2bfloat16(av.w - __bfloat162float(h3));
            uint32_t* ph = reinterpret_cast<uint32_t*>(sAhi + row * SA + kg);
            uint32_t* pl = reinterpret_cast<uint32_t*>(sAlo + row * SA + kg);
            ph[0] = pk(h0, h1); ph[1] = pk(h2, h3);
            pl[0] = pk(l0, l1); pl[1] = pk(l2, l3);
        }
        // ---- fill B tile transposed: sB[n][k], 128 n x 32 k ----
#pragma unroll
        for (int li = 0; li < 4; li++) {
            const int idx = tid + li * 256;        // 0..1023
            const int n = idx & 127;
            const int kq = idx >> 7;               // 0..7
            const int kb = kq * 4;
            float v0 = B[(size_t)(k0 + kb + 0) * N + bn + n];
            float v1 = B[(size_t)(k0 + kb + 1) * N + bn + n];
            float v2 = B[(size_t)(k0 + kb + 2) * N + bn + n];
            float v3 = B[(size_t)(k0 + kb + 3) * N + bn + n];
            __nv_bfloat16 h0 = __float2bfloat16(v0);
            __nv_bfloat16 h1 = __float2bfloat16(v1);
            __nv_bfloat16 h2 = __float2bfloat16(v2);
            __nv_bfloat16 h3 = __float2bfloat16(v3);
            __nv_bfloat16 l0 = __float2bfloat16(v0 - __bfloat162float(h0));
            __nv_bfloat16 l1 = __float2bfloat16(v1 - __bfloat162float(h1));
            __nv_bfloat16 l2 = __float2bfloat16(v2 - __bfloat162float(h2));
            __nv_bfloat16 l3 = __float2bfloat16(v3 - __bfloat162float(h3));
            uint32_t* ph = reinterpret_cast<uint32_t*>(sBhi + n * SB + kb);
            uint32_t* pl = reinterpret_cast<uint32_t*>(sBlo + n * SB + kb);
            ph[0] = pk(h0, h1); ph[1] = pk(h2, h3);
            pl[0] = pk(l0, l1); pl[1] = pk(l2, l3);
        }
        __syncthreads();

        // ---- compute: 2 k-steps of 16 ----
#pragma unroll
        for (int ks = 0; ks < 2; ks++) {
            const int koff = ks * 16 + 2 * t;
            uint32_t bh[4][2], bl[4][2];
#pragma unroll
            for (int ni = 0; ni < 4; ni++) {
                const int nb = wn * 32 + ni * 8 + g;
                bh[ni][0] = *reinterpret_cast<const uint32_t*>(sBhi + nb * SB + koff);
                bh[ni][1] = *reinterpret_cast<const uint32_t*>(sBhi + nb * SB + koff + 8);
                bl[ni][0] = *reinterpret_cast<const uint32_t*>(sBlo + nb * SB + koff);
                bl[ni][1] = *reinterpret_cast<const uint32_t*>(sBlo + nb * SB + koff + 8);
            }
#pragma unroll
            for (int mi = 0; mi < 4; mi++) {
                const int rb = wm * 64 + mi * 16 + g;
                uint32_t ah[4], al[4];
                ah[0] = *reinterpret_cast<const uint32_t*>(sAhi + rb * SA + koff);
                ah[1] = *reinterpret_cast<const uint32_t*>(sAhi + (rb + 8) * SA + koff);
                ah[2] = *reinterpret_cast<const uint32_t*>(sAhi + rb * SA + koff + 8);
                ah[3] = *reinterpret_cast<const uint32_t*>(sAhi + (rb + 8) * SA + koff + 8);
                al[0] = *reinterpret_cast<const uint32_t*>(sAlo + rb * SA + koff);
                al[1] = *reinterpret_cast<const uint32_t*>(sAlo + (rb + 8) * SA + koff);
                al[2] = *reinterpret_cast<const uint32_t*>(sAlo + rb * SA + koff + 8);
                al[3] = *reinterpret_cast<const uint32_t*>(sAlo + (rb + 8) * SA + koff + 8);
#pragma unroll
                for (int ni = 0; ni < 4; ni++) {
                    mma16816(acc[mi][ni], ah, bh[ni]);
                    mma16816(acc[mi][ni], ah, bl[ni]);
                    mma16816(acc[mi][ni], al, bh[ni]);
                }
            }
        }
        __syncthreads();
    }

    // ---- epilogue ----
#pragma unroll
    for (int mi = 0; mi < 4; mi++) {
        const int row0 = bm + wm * 64 + mi * 16 + g;
#pragma unroll
        for (int ni = 0; ni < 4; ni++) {
            const int col = bn + wn * 32 + ni * 8 + 2 * t;
            float c0 = acc[mi][ni][0], c1 = acc[mi][ni][1];
            float c2 = acc[mi][ni][2], c3 = acc[mi][ni][3];
            if (BIAS) {
                const float b0 = bias[col], b1 = bias[col + 1];
                c0 += b0; c1 += b1; c2 += b0; c3 += b1;
            }
            if (RELU) {
                c0 = fmaxf(c0, 0.f); c1 = fmaxf(c1, 0.f);
                c2 = fmaxf(c2, 0.f); c3 = fmaxf(c3, 0.f);
            }
            if (row0 < M)
                *reinterpret_cast<float2*>(Cout + (size_t)row0 * N + col) = make_float2(c0, c1);
            if (row0 + 8 < M)
                *reinterpret_cast<float2*>(Cout + (size_t)(row0 + 8) * N + col) = make_float2(c2, c3);
        }
    }
}

// ---------------- per-(node,head) attention logit ----------------
__global__ void alpha_kernel(const float* __restrict__ p, const float* __restrict__ att,
                             float* __restrict__ out, int N) {
    const int gw = (blockIdx.x * blockDim.x + threadIdx.x) >> 5;
    const int lane = threadIdx.x & 31;
    if (gw >= N * H) return;
    const int n = gw >> 2;
    const int h = gw & 3;
    const float* pr = p + (size_t)n * HID + h * 64;
    const float* at = att + h * 64;
    float s = pr[lane] * at[lane] + pr[lane + 32] * at[lane + 32];
#pragma unroll
    for (int o = 16; o > 0; o >>= 1) s += __shfl_down_sync(0xffffffffu, s, o);
    if (lane == 0) out[gw] = s;
}

__device__ __forceinline__ void atomicMaxFloat(float* addr, float value) {
    if (value >= 0.f)
        atomicMax(reinterpret_cast<int*>(addr), __float_as_int(value));
    else
        atomicMin(reinterpret_cast<unsigned int*>(addr), __float_as_uint(value));
}

__global__ void fill_neg_inf(float* __restrict__ p, int n) {
    const int i = blockIdx.x * blockDim.x + threadIdx.x;
    if (i < n) p[i] = __int_as_float(0xff800000);
}

// ---------------- edge pass 1: segment max ----------------
__global__ void edge_max_kernel(const int* __restrict__ src, const int* __restrict__ dst,
                                int E, int nLoops,
                                const float* __restrict__ as_, const float* __restrict__ ad_,
                                float* __restrict__ m) {
    const int e = blockIdx.x * blockDim.x + threadIdx.x;
    const int total = E + nLoops;
    if (e >= total) return;
    int s, d;
    if (e < E) { s = src[e]; d = dst[e]; }
    else { s = e - E; d = s; }
    const float4 a4 = reinterpret_cast<const float4*>(as_)[s];
    const float4 b4 = reinterpret_cast<const float4*>(ad_)[d];
    float a;
    a = a4.x + b4.x; a = a > 0.f ? a : 0.2f * a; atomicMaxFloat(&m[d * 4 + 0], a);
    a = a4.y + b4.y; a = a > 0.f ? a : 0.2f * a; atomicMaxFloat(&m[d * 4 + 1], a);
    a = a4.z + b4.z; a = a > 0.f ? a : 0.2f * a; atomicMaxFloat(&m[d * 4 + 2], a);
    a = a4.w + b4.w; a = a > 0.f ? a : 0.2f * a; atomicMaxFloat(&m[d * 4 + 3], a);
}

// ---------------- edge pass 2: exp + weighted scatter (one warp/edge) ----------
// vectorized: 2x red.global.add.v4.f32 per lane
__global__ void edge_sum_kernel(const int* __restrict__ src, const int* __restrict__ dst,
                                int E, int nLoops,
                                const float* __restrict__ as_, const float* __restrict__ ad_,
                                const float* __restrict__ m,
                                const float* __restrict__ xs,
                                float* __restrict__ den, float* __restrict__ msg) {
    const int gw = (blockIdx.x * blockDim.x + threadIdx.x) >> 5;
    const int lane = threadIdx.x & 31;
    const int total = E + nLoops;
    if (gw >= total) return;
    int s, d;
    if (gw < E) { s = src[gw]; d = dst[gw]; }
    else { s = gw - E; d = s; }

    float ex = 0.f;
    if (lane < 4) {
        float a = as_[s * 4 + lane] + ad_[d * 4 + lane];
        a = a > 0.f ? a : 0.2f * a;
        ex = expf(a - m[d * 4 + lane]);
        atomicAdd(&den[d * 4 + lane], ex);
    }
    const float w0 = __shfl_sync(0xffffffffu, ex, lane >> 4);        // heads 0/1
    const float w1 = __shfl_sync(0xffffffffu, ex, 2 + (lane >> 4));  // heads 2/3

    const float* xr = xs + (size_t)s * HID;
    float* mr = msg + (size_t)d * HID;

    const int k0 = lane * 4;
    float4 x0 = *reinterpret_cast<const float4*>(xr + k0);
    float4 x1 = *reinterpret_cast<const float4*>(xr + 128 + k0);
    asm volatile("red.global.add.v4.f32 [%0], {%1,%2,%3,%4};" ::
                 "l"(mr + k0), "f"(w0 * x0.x), "f"(w0 * x0.y),
                 "f"(w0 * x0.z), "f"(w0 * x0.w) : "memory");
    asm volatile("red.global.add.v4.f32 [%0], {%1,%2,%3,%4};" ::
                 "l"(mr + 128 + k0), "f"(w1 * x1.x), "f"(w1 * x1.y),
                 "f"(w1 * x1.z), "f"(w1 * x1.w) : "memory");
}

// ---------------- combine: x = relu(0.25*o1 + 0.25*o2 + 0.5*o3 + ht) ----------
__global__ void combine_kernel(const float* __restrict__ msg0, const float* __restrict__ msg1,
                               const float* __restrict__ msg2, const float* __restrict__ den,
                               const float* __restrict__ b1, const float* __restrict__ b2,
                               const float* __restrict__ b3,
                               const float* __restrict__ ht, float* __restrict__ xout) {
    const int idx = blockIdx.x * blockDim.x + threadIdx.x;
    if (idx >= NT * HID) return;
    const int n = idx >> 8;
    const int k = idx & 255;
    const int h = k >> 6;
    const float d0 = fmaxf(den[0 * NT * H + n * 4 + h], 1e-16f);
    const float d1 = fmaxf(den[1 * NT * H + n * 4 + h], 1e-16f);
    const float d2 = fmaxf(den[2 * NT * H + n * 4 + h], 1e-16f);
    const float o1 = msg0[idx] / d0 + b1[k];
    const float o2 = msg1[idx] / d1 + b2[k];
    const float o3 = msg2[idx] / d2 + b3[k];
    float x = 0.25f * (o1 + o2) + 0.5f * o3;
    x += ht[idx];
    xout[idx] = fmaxf(x, 0.f);
}

// ---------------- launch ----------------
extern "C" void kernel_launch(void* const* d_in, const int* in_sizes, int n_in,
                              void* d_out, int out_size) {
    const float* x_target = (const float*)d_in[0];
    const float* x_context = (const float*)d_in[1];
    const int*   ei_tt     = (const int*)d_in[2];      // [2, E_TT]
    const int*   ei_ct_src = (const int*)d_in[3];
    const int*   ei_ct_dst = (const int*)d_in[4];
    const float* Wt = (const float*)d_in[5];
    const float* bt = (const float*)d_in[6];
    const float* Wc = (const float*)d_in[7];
    const float* bc = (const float*)d_in[8];
    const float* W_s2d  = (const float*)d_in[9];
    const float* as_s2d = (const float*)d_in[10];
    const float* ad_s2d = (const float*)d_in[11];
    const float* b_s2d  = (const float*)d_in[12];
    const float* W_d2s  = (const float*)d_in[13];
    const float* as_d2s = (const float*)d_in[14];
    const float* ad_d2s = (const float*)d_in[15];
    const float* b_d2s  = (const float*)d_in[16];
    const float* W_ct_src = (const float*)d_in[17];
    const float* W_ct_dst = (const float*)d_in[18];
    const float* as_ct  = (const float*)d_in[19];
    const float* ad_ct  = (const float*)d_in[20];
    const float* b_ct   = (const float*)d_in[21];
    const float* W_out  = (const float*)d_in[22];
    const float* b_out  = (const float*)d_in[23];

    float *ht, *hc, *p1, *p2, *pd, *ps, *msg0, *msg1, *msg2, *den, *m, *as_, *ad_, *xb;
    cudaGetSymbolAddress((void**)&ht,   g_ht);
    cudaGetSymbolAddress((void**)&hc,   g_hc);
    cudaGetSymbolAddress((void**)&p1,   g_p1);
    cudaGetSymbolAddress((void**)&p2,   g_p2);
    cudaGetSymbolAddress((void**)&pd,   g_pd);
    cudaGetSymbolAddress((void**)&ps,   g_ps);
    cudaGetSymbolAddress((void**)&msg0, g_msg0);
    cudaGetSymbolAddress((void**)&msg1, g_msg1);
    cudaGetSymbolAddress((void**)&msg2, g_msg2);
    cudaGetSymbolAddress((void**)&den,  g_den);
    cudaGetSymbolAddress((void**)&m,    g_m);
    cudaGetSymbolAddress((void**)&as_,  g_as);
    cudaGetSymbolAddress((void**)&ad_,  g_ad);
    cudaGetSymbolAddress((void**)&xb,   g_x);

    // zero accumulators, fill segment-max with -inf
    cudaMemsetAsync(msg0, 0, sizeof(float) * NT * HID, 0);
    cudaMemsetAsync(msg1, 0, sizeof(float) * NT * HID, 0);
    cudaMemsetAsync(msg2, 0, sizeof(float) * NT * HID, 0);
    cudaMemsetAsync(den,  0, sizeof(float) * 3 * NT * H, 0);
    {
        const int n = 3 * NT * H;
        fill_neg_inf<<<(n + 255) / 256, 256>>>(m, n);
    }

    const dim3 blk(256);
    const dim3 g_nt(HID / 128, (NT + 127) / 128);
    const dim3 g_nc(HID / 128, (NC + 127) / 128);

    // pretransform + relu
    mma_gemm<true, true><<<g_nt, blk>>>(x_target, Wt, bt, ht, NT, HID, FT);
    mma_gemm<true, true><<<g_nc, blk>>>(x_context, Wc, bc, hc, NC, HID, FC);

    // projections
    mma_gemm<false, false><<<g_nt, blk>>>(ht, W_s2d,   nullptr, p1, NT, HID, HID);
    mma_gemm<false, false><<<g_nt, blk>>>(ht, W_d2s,   nullptr, p2, NT, HID, HID);
    mma_gemm<false, false><<<g_nt, blk>>>(ht, W_ct_dst, nullptr, pd, NT, HID, HID);
    mma_gemm<false, false><<<g_nc, blk>>>(hc, W_ct_src, nullptr, ps, NC, HID, HID);

    const int* tt_src = ei_tt;
    const int* tt_dst = ei_tt + E_TT;

    const int aw_nt = NT * H * 32;
    const int aw_nc = NC * H * 32;
    const int ett_total = E_TT + NT;                // with self loops
    const int ett_warp_threads = ett_total * 32;
    const int ect_warp_threads = E_CT * 32;

    // ---- graph 0: s2d (src->dst), xs = xd = p1 ----
    alpha_kernel<<<(aw_nt + 255) / 256, 256>>>(p1, as_s2d, as_, NT);
    alpha_kernel<<<(aw_nt + 255) / 256, 256>>>(p1, ad_s2d, ad_, NT);
    edge_max_kernel<<<(ett_total + 255) / 256, 256>>>(tt_src, tt_dst, E_TT, NT, as_, ad_, m);
    edge_sum_kernel<<<(ett_warp_threads + 255) / 256, 256>>>(
        tt_src, tt_dst, E_TT, NT, as_, ad_, m, p1, den, msg0);

    // ---- graph 1: d2s (reversed edges), xs = xd = p2 ----
    alpha_kernel<<<(aw_nt + 255) / 256, 256>>>(p2, as_d2s, as_, NT);
    alpha_kernel<<<(aw_nt + 255) / 256, 256>>>(p2, ad_d2s, ad_, NT);
    edge_max_kernel<<<(ett_total + 255) / 256, 256>>>(tt_dst, tt_src, E_TT, NT, as_, ad_,
                                                      m + NT * H);
    edge_sum_kernel<<<(ett_warp_threads + 255) / 256, 256>>>(
        tt_dst, tt_src, E_TT, NT, as_, ad_, m + NT * H, p2, den + NT * H, msg1);

    // ---- graph 2: context -> target bipartite ----
    alpha_kernel<<<(aw_nc + 255) / 256, 256>>>(ps, as_ct, as_, NC);
    alpha_kernel<<<(aw_nt + 255) / 256, 256>>>(pd, ad_ct, ad_, NT);
    edge_max_kernel<<<(E_CT + 255) / 256, 256>>>(ei_ct_src, ei_ct_dst, E_CT, 0, as_, ad_,
                                                 m + 2 * NT * H);
    edge_sum_kernel<<<(ect_warp_threads + 255) / 256, 256>>>(
        ei_ct_src, ei_ct_dst, E_CT, 0, as_, ad_, m + 2 * NT * H, ps, den + 2 * NT * H, msg2);

    // ---- combine + skip + relu ----
    combine_kernel<<<(NT * HID + 255) / 256, 256>>>(msg0, msg1, msg2, den,
                                                    b_s2d, b_d2s, b_ct, ht, xb);

    // ---- final linear ----
    mma_gemm<true, false><<<g_nt, blk>>>(xb, W_out, b_out, (float*)d_out, NT, HID, HID);
}

// round 4
// speedup vs baseline: 1.4973x; 1.1792x over previous
#include <cuda_runtime.h>
#include <cuda_bf16.h>
#include <math.h>
#include <stdint.h>

typedef unsigned long long ull;

// ---------------- problem constants ----------------
constexpr int NT  = 50000;
constexpr int NC  = 10000;
constexpr int H   = 4;
constexpr int C   = 64;
constexpr int HID = 256;       // H*C
constexpr int E_TT = 400000;
constexpr int E_CT = 200000;
constexpr int FT = 128;
constexpr int FC = 64;

// ---------------- device scratch ----------------
// fp32
__device__ float g_ht[NT * HID];
__device__ float g_p1[NT * HID];
__device__ float g_p2[NT * HID];
__device__ float g_pd[NT * HID];
__device__ float g_ps[NC * HID];
__device__ float g_msg0[NT * HID];
__device__ float g_msg1[NT * HID];
__device__ float g_msg2[NT * HID];
__device__ float g_den[3 * NT * H];
__device__ float g_as0[NT * H];
__device__ float g_ad0[NT * H];
__device__ float g_as1[NT * H];
__device__ float g_ad1[NT * H];
__device__ float g_as2[NC * H];
__device__ float g_ad2[NT * H];
// bf16 hi/lo activations
__device__ __nv_bfloat16 g_xt_hi[NT * FT],  g_xt_lo[NT * FT];
__device__ __nv_bfloat16 g_xc_hi[NC * FC],  g_xc_lo[NC * FC];
__device__ __nv_bfloat16 g_ht_hi[NT * HID], g_ht_lo[NT * HID];
__device__ __nv_bfloat16 g_hc_hi[NC * HID], g_hc_lo[NC * HID];
__device__ __nv_bfloat16 g_xb_hi[NT * HID], g_xb_lo[NT * HID];
// bf16 hi/lo transposed weights [N, K]
__device__ __nv_bfloat16 g_wt_hi[HID * FT],  g_wt_lo[HID * FT];
__device__ __nv_bfloat16 g_wc_hi[HID * FC],  g_wc_lo[HID * FC];
__device__ __nv_bfloat16 g_w1_hi[HID * HID], g_w1_lo[HID * HID];
__device__ __nv_bfloat16 g_w2_hi[HID * HID], g_w2_lo[HID * HID];
__device__ __nv_bfloat16 g_wd_hi[HID * HID], g_wd_lo[HID * HID];
__device__ __nv_bfloat16 g_ws_hi[HID * HID], g_ws_lo[HID * HID];
__device__ __nv_bfloat16 g_wo_hi[HID * HID], g_wo_lo[HID * HID];

__device__ __forceinline__ uint32_t pk(__nv_bfloat16 a, __nv_bfloat16 b) {
    return (uint32_t)__bfloat16_as_ushort(a) | ((uint32_t)__bfloat16_as_ushort(b) << 16);
}
__device__ __forceinline__ void split1(float v, __nv_bfloat16& h, __nv_bfloat16& l) {
    h = __float2bfloat16(v);
    l = __float2bfloat16(v - __bfloat162float(h));
}

// ---------------- conversion kernels ----------------
__global__ void split_kernel(const float* __restrict__ src,
                             __nv_bfloat16* __restrict__ hi, __nv_bfloat16* __restrict__ lo,
                             int n4) {
    const int i4 = blockIdx.x * blockDim.x + threadIdx.x;
    if (i4 >= n4) return;
    const int i = i4 * 4;
    const float4 v = *reinterpret_cast<const float4*>(src + i);
    __nv_bfloat16 h0, h1, h2, h3, l0, l1, l2, l3;
    split1(v.x, h0, l0); split1(v.y, h1, l1);
    split1(v.z, h2, l2); split1(v.w, h3, l3);
    uint32_t* ph = reinterpret_cast<uint32_t*>(hi + i);
    uint32_t* pl = reinterpret_cast<uint32_t*>(lo + i);
    ph[0] = pk(h0, h1); ph[1] = pk(h2, h3);
    pl[0] = pk(l0, l1); pl[1] = pk(l2, l3);
}

// weight [K, N] fp32 -> hi/lo [N, K] bf16
__global__ void splitT_kernel(const float* __restrict__ W,
                              __nv_bfloat16* __restrict__ hi, __nv_bfloat16* __restrict__ lo,
                              int K, int N) {
    const int idx = blockIdx.x * blockDim.x + threadIdx.x;
    if (idx >= K * N) return;
    const int k = idx / N, n = idx % N;
    __nv_bfloat16 h, l;
    split1(W[idx], h, l);
    hi[n * K + k] = h;
    lo[n * K + k] = l;
}

// ================= bf16 double-split tensor-core GEMM v2 =================
// C = A @ B^T with A hi/lo [M,K] bf16, B hi/lo [N,K] bf16 (pre-transposed).
// CTA 128x128, BK=32, 512 threads (16 warps 4x4), warp tile 32x32.
// cp.async double-buffered. Dynamic smem 80KB.

constexpr int SA = 40;                       // smem row stride (bf16)
constexpr int TILE_ARR = 128 * SA;           // one array
constexpr int OFF_AHI = 0;
constexpr int OFF_ALO = TILE_ARR;
constexpr int OFF_BHI = 2 * TILE_ARR;
constexpr int OFF_BLO = 3 * TILE_ARR;
constexpr int BUF_STRIDE = 4 * TILE_ARR;     // bf16 units
constexpr int GEMM_SMEM = 2 * BUF_STRIDE * 2;  // bytes = 81920

__device__ __forceinline__ void cp16(__nv_bfloat16* smem, const __nv_bfloat16* gmem) {
    uint32_t sa = (uint32_t)__cvta_generic_to_shared(smem);
    asm volatile("cp.async.ca.shared.global [%0], [%1], 16;" :: "r"(sa), "l"(gmem));
}

__device__ __forceinline__ void mma16816(float* c, const uint32_t* a, const uint32_t* b) {
    asm volatile(
        "mma.sync.aligned.m16n8k16.row.col.f32.bf16.bf16.f32 "
        "{%0,%1,%2,%3}, {%4,%5,%6,%7}, {%8,%9}, {%0,%1,%2,%3};"
        : "+f"(c[0]), "+f"(c[1]), "+f"(c[2]), "+f"(c[3])
        : "r"(a[0]), "r"(a[1]), "r"(a[2]), "r"(a[3]), "r"(b[0]), "r"(b[1]));
}

template <bool BIAS, bool RELU, bool WF32, bool WBF16>
__global__ void __launch_bounds__(512, 1) mma_gemm2(
        const __nv_bfloat16* __restrict__ Ahi, const __nv_bfloat16* __restrict__ Alo,
        const __nv_bfloat16* __restrict__ Bhi, const __nv_bfloat16* __restrict__ Blo,
        const float* __restrict__ bias,
        float* __restrict__ Cf32, __nv_bfloat16* __restrict__ Chi,
        __nv_bfloat16* __restrict__ Clo,
        int M, int N, int K) {
    extern __shared__ __align__(16) char dynsmem[];
    __nv_bfloat16* sm = reinterpret_cast<__nv_bfloat16*>(dynsmem);

    const int tid = threadIdx.x;
    const int bm = blockIdx.y * 128;
    const int bn = blockIdx.x * 128;
    const int wid = tid >> 5;
    const int lane = tid & 31;
    const int wm = wid >> 2;          // 0..3 -> 32 rows
    const int wn = wid & 3;           // 0..3 -> 32 cols
    const int g = lane >> 2;          // 0..7
    const int t = lane & 3;           // 0..3

    // fill indices
    const int frow = tid >> 2;              // 0..127
    const int fkc  = (tid & 3) * 8;         // bf16 offset in tile row
    int garow = bm + frow; if (garow >= M) garow = M - 1;
    const int gbrow = bn + frow;            // always < N (N multiple of 128)

    float acc[2][4][4];
#pragma unroll
    for (int mi = 0; mi < 2; mi++)
#pragma unroll
        for (int ni = 0; ni < 4; ni++)
#pragma unroll
            for (int r = 0; r < 4; r++) acc[mi][ni][r] = 0.f;

    const int KT = K >> 5;

    // prologue: load tile 0 into buf 0
    {
        const size_t ao = (size_t)garow * K + fkc;
        const size_t bo = (size_t)gbrow * K + fkc;
        __nv_bfloat16* b0 = sm;
        cp16(b0 + OFF_AHI + frow * SA + fkc, Ahi + ao);
        cp16(b0 + OFF_ALO + frow * SA + fkc, Alo + ao);
        cp16(b0 + OFF_BHI + frow * SA + fkc, Bhi + bo);
        cp16(b0 + OFF_BLO + frow * SA + fkc, Blo + bo);
        asm volatile("cp.async.commit_group;");
    }

    for (int kt = 0; kt < KT; kt++) {
        asm volatile("cp.async.wait_group 0;");
        __syncthreads();
        if (kt + 1 < KT) {
            const int k0 = (kt + 1) << 5;
            const size_t ao = (size_t)garow * K + k0 + fkc;
            const size_t bo = (size_t)gbrow * K + k0 + fkc;
            __nv_bfloat16* nb = sm + ((kt + 1) & 1) * BUF_STRIDE;
            cp16(nb + OFF_AHI + frow * SA + fkc, Ahi + ao);
            cp16(nb + OFF_ALO + frow * SA + fkc, Alo + ao);
            cp16(nb + OFF_BHI + frow * SA + fkc, Bhi + bo);
            cp16(nb + OFF_BLO + frow * SA + fkc, Blo + bo);
            asm volatile("cp.async.commit_group;");
        }
        const __nv_bfloat16* cb = sm + (kt & 1) * BUF_STRIDE;
        const __nv_bfloat16* sAhi = cb + OFF_AHI;
        const __nv_bfloat16* sAlo = cb + OFF_ALO;
        const __nv_bfloat16* sBhi = cb + OFF_BHI;
        const __nv_bfloat16* sBlo = cb + OFF_BLO;

#pragma unroll
        for (int ks = 0; ks < 2; ks++) {
            const int koff = ks * 16 + 2 * t;
            uint32_t bh[4][2], bl[4][2];
#pragma unroll
            for (int ni = 0; ni < 4; ni++) {
                const int nb = wn * 32 + ni * 8 + g;
                bh[ni][0] = *reinterpret_cast<const uint32_t*>(sBhi + nb * SA + koff);
                bh[ni][1] = *reinterpret_cast<const uint32_t*>(sBhi + nb * SA + koff + 8);
                bl[ni][0] = *reinterpret_cast<const uint32_t*>(sBlo + nb * SA + koff);
                bl[ni][1] = *reinterpret_cast<const uint32_t*>(sBlo + nb * SA + koff + 8);
            }
#pragma unroll
            for (int mi = 0; mi < 2; mi++) {
                const int rb = wm * 32 + mi * 16 + g;
                uint32_t ah[4], al[4];
                ah[0] = *reinterpret_cast<const uint32_t*>(sAhi + rb * SA + koff);
                ah[1] = *reinterpret_cast<const uint32_t*>(sAhi + (rb + 8) * SA + koff);
                ah[2] = *reinterpret_cast<const uint32_t*>(sAhi + rb * SA + koff + 8);
                ah[3] = *reinterpret_cast<const uint32_t*>(sAhi + (rb + 8) * SA + koff + 8);
                al[0] = *reinterpret_cast<const uint32_t*>(sAlo + rb * SA + koff);
                al[1] = *reinterpret_cast<const uint32_t*>(sAlo + (rb + 8) * SA + koff);
                al[2] = *reinterpret_cast<const uint32_t*>(sAlo + rb * SA + koff + 8);
                al[3] = *reinterpret_cast<const uint32_t*>(sAlo + (rb + 8) * SA + koff + 8);
#pragma unroll
                for (int ni = 0; ni < 4; ni++) {
                    mma16816(acc[mi][ni], ah, bh[ni]);
                    mma16816(acc[mi][ni], ah, bl[ni]);
                    mma16816(acc[mi][ni], al, bh[ni]);
                }
            }
        }
        __syncthreads();
    }

    // ---- epilogue ----
#pragma unroll
    for (int mi = 0; mi < 2; mi++) {
        const int row0 = bm + wm * 32 + mi * 16 + g;
#pragma unroll
        for (int ni = 0; ni < 4; ni++) {
            const int col = bn + wn * 32 + ni * 8 + 2 * t;
            float c0 = acc[mi][ni][0], c1 = acc[mi][ni][1];
            float c2 = acc[mi][ni][2], c3 = acc[mi][ni][3];
            if (BIAS) {
                const float b0 = bias[col], b1 = bias[col + 1];
                c0 += b0; c1 += b1; c2 += b0; c3 += b1;
            }
            if (RELU) {
                c0 = fmaxf(c0, 0.f); c1 = fmaxf(c1, 0.f);
                c2 = fmaxf(c2, 0.f); c3 = fmaxf(c3, 0.f);
            }
#pragma unroll
            for (int rr = 0; rr < 2; rr++) {
                const int row = row0 + rr * 8;
                if (row >= M) continue;
                const float v0 = rr ? c2 : c0;
                const float v1 = rr ? c3 : c1;
                const size_t off = (size_t)row * N + col;
                if (WF32)
                    *reinterpret_cast<float2*>(Cf32 + off) = make_float2(v0, v1);
                if (WBF16) {
                    __nv_bfloat16 h0, h1, l0, l1;
                    split1(v0, h0, l0); split1(v1, h1, l1);
                    *reinterpret_cast<uint32_t*>(Chi + off) = pk(h0, h1);
                    *reinterpret_cast<uint32_t*>(Clo + off) = pk(l0, l1);
                }
            }
        }
    }
}

// ---------------- alpha kernels ----------------
__global__ void alpha_kernel(const float* __restrict__ p, const float* __restrict__ att,
                             float* __restrict__ out, int N) {
    const int gw = (blockIdx.x * blockDim.x + threadIdx.x) >> 5;
    const int lane = threadIdx.x & 31;
    if (gw >= N * H) return;
    const int n = gw >> 2;
    const int h = gw & 3;
    const float* pr = p + (size_t)n * HID + h * 64;
    const float* at = att + h * 64;
    float s = pr[lane] * at[lane] + pr[lane + 32] * at[lane + 32];
#pragma unroll
    for (int o = 16; o > 0; o >>= 1) s += __shfl_xor_sync(0xffffffffu, s, o);
    if (lane == 0) out[gw] = s;
}

__global__ void alpha01_kernel(const float* __restrict__ p1, const float* __restrict__ p2,
                               const float* __restrict__ a_s0, const float* __restrict__ a_d0,
                               const float* __restrict__ a_s1, const float* __restrict__ a_d1,
                               float* __restrict__ as0, float* __restrict__ ad0,
                               float* __restrict__ as1, float* __restrict__ ad1) {
    const int gw = (blockIdx.x * blockDim.x + threadIdx.x) >> 5;
    const int lane = threadIdx.x & 31;
    if (gw >= NT * H) return;
    const int n = gw >> 2;
    const int h = gw & 3;
    const float* r1 = p1 + (size_t)n * HID + h * 64;
    const float* r2 = p2 + (size_t)n * HID + h * 64;
    const float x1a = r1[lane], x1b = r1[lane + 32];
    const float x2a = r2[lane], x2b = r2[lane + 32];
    const float* v;
    v = a_s0 + h * 64; float s0 = x1a * v[lane] + x1b * v[lane + 32];
    v = a_d0 + h * 64; float s1 = x1a * v[lane] + x1b * v[lane + 32];
    v = a_s1 + h * 64; float s2 = x2a * v[lane] + x2b * v[lane + 32];
    v = a_d1 + h * 64; float s3 = x2a * v[lane] + x2b * v[lane + 32];
#pragma unroll
    for (int o = 16; o > 0; o >>= 1) {
        s0 += __shfl_xor_sync(0xffffffffu, s0, o);
        s1 += __shfl_xor_sync(0xffffffffu, s1, o);
        s2 += __shfl_xor_sync(0xffffffffu, s2, o);
        s3 += __shfl_xor_sync(0xffffffffu, s3, o);
    }
    if (lane == 0) { as0[gw] = s0; ad0[gw] = s1; as1[gw] = s2; ad1[gw] = s3; }
}

// ---------------- fused edge pass for both tt directions (no segment-max) ----
__global__ void edge01_kernel(const int* __restrict__ src, const int* __restrict__ dst,
                              const float* __restrict__ as0, const float* __restrict__ ad0,
                              const float* __restrict__ as1, const float* __restrict__ ad1,
                              const float* __restrict__ p1, const float* __restrict__ p2,
                              float* __restrict__ den0, float* __restrict__ den1,
                              float* __restrict__ msg0, float* __restrict__ msg1) {
    const int gw = (blockIdx.x * blockDim.x + threadIdx.x) >> 5;
    const int lane = threadIdx.x & 31;
    const int total = E_TT + NT;
    if (gw >= total) return;
    int s, d;
    if (gw < E_TT) { s = src[gw]; d = dst[gw]; }
    else { s = gw - E_TT; d = s; }

    float ex = 0.f;
    if (lane < 4) {
        float a = as0[s * 4 + lane] + ad0[d * 4 + lane];
        a = a > 0.f ? a : 0.2f * a;
        ex = __expf(a);
        atomicAdd(&den0[d * 4 + lane], ex);
    } else if (lane < 8) {
        const int h = lane - 4;
        float a = as1[d * 4 + h] + ad1[s * 4 + h];
        a = a > 0.f ? a : 0.2f * a;
        ex = __expf(a);
        atomicAdd(&den1[s * 4 + h], ex);
    }
    const int hs = lane >> 4;
    const float w00 = __shfl_sync(0xffffffffu, ex, hs);
    const float w01 = __shfl_sync(0xffffffffu, ex, 2 + hs);
    const float w10 = __shfl_sync(0xffffffffu, ex, 4 + hs);
    const float w11 = __shfl_sync(0xffffffffu, ex, 6 + hs);

    const int k0 = lane * 4;
    const float* xr0 = p1 + (size_t)s * HID;
    float* mr0 = msg0 + (size_t)d * HID;
    const float4 x0 = *reinterpret_cast<const float4*>(xr0 + k0);
    const float4 x1 = *reinterpret_cast<const float4*>(xr0 + 128 + k0);
    asm volatile("red.global.add.v4.f32 [%0], {%1,%2,%3,%4};" ::
                 "l"(mr0 + k0), "f"(w00 * x0.x), "f"(w00 * x0.y),
                 "f"(w00 * x0.z), "f"(w00 * x0.w) : "memory");
    asm volatile("red.global.add.v4.f32 [%0], {%1,%2,%3,%4};" ::
                 "l"(mr0 + 128 + k0), "f"(w01 * x1.x), "f"(w01 * x1.y),
                 "f"(w01 * x1.z), "f"(w01 * x1.w) : "memory");

    const float* xr1 = p2 + (size_t)d * HID;
    float* mr1 = msg1 + (size_t)s * HID;
    const float4 y0 = *reinterpret_cast<const float4*>(xr1 + k0);
    const float4 y1 = *reinterpret_cast<const float4*>(xr1 + 128 + k0);
    asm volatile("red.global.add.v4.f32 [%0], {%1,%2,%3,%4};" ::
                 "l"(mr1 + k0), "f"(w10 * y0.x), "f"(w10 * y0.y),
                 "f"(w10 * y0.z), "f"(w10 * y0.w) : "memory");
    asm volatile("red.global.add.v4.f32 [%0], {%1,%2,%3,%4};" ::
                 "l"(mr1 + 128 + k0), "f"(w11 * y1.x), "f"(w11 * y1.y),
                 "f"(w11 * y1.z), "f"(w11 * y1.w) : "memory");
}

// ---------------- bipartite edge pass (no segment-max) ----------------
__global__ void edge2_kernel(const int* __restrict__ src, const int* __restrict__ dst,
                             const float* __restrict__ as_, const float* __restrict__ ad_,
                             const float* __restrict__ xs,
                             float* __restrict__ den, float* __restrict__ msg) {
    const int gw = (blockIdx.x * blockDim.x + threadIdx.x) >> 5;
    const int lane = threadIdx.x & 31;
    if (gw >= E_CT) return;
    const int s = src[gw];
    const int d = dst[gw];

    float ex = 0.f;
    if (lane < 4) {
        float a = as_[s * 4 + lane] + ad_[d * 4 + lane];
        a = a > 0.f ? a : 0.2f * a;
        ex = __expf(a);
        atomicAdd(&den[d * 4 + lane], ex);
    }
    const int hs = lane >> 4;
    const float w0 = __shfl_sync(0xffffffffu, ex, hs);
    const float w1 = __shfl_sync(0xffffffffu, ex, 2 + hs);

    const float* xr = xs + (size_t)s * HID;
    float* mr = msg + (size_t)d * HID;
    const int k0 = lane * 4;
    const float4 x0 = *reinterpret_cast<const float4*>(xr + k0);
    const float4 x1 = *reinterpret_cast<const float4*>(xr + 128 + k0);
    asm volatile("red.global.add.v4.f32 [%0], {%1,%2,%3,%4};" ::
                 "l"(mr + k0), "f"(w0 * x0.x), "f"(w0 * x0.y),
                 "f"(w0 * x0.z), "f"(w0 * x0.w) : "memory");
    asm volatile("red.global.add.v4.f32 [%0], {%1,%2,%3,%4};" ::
                 "l"(mr + 128 + k0), "f"(w1 * x1.x), "f"(w1 * x1.y),
                 "f"(w1 * x1.z), "f"(w1 * x1.w) : "memory");
}

// ---------------- combine -> xb (bf16 hi/lo directly) ----------------
__global__ void combine_kernel(const float* __restrict__ msg0, const float* __restrict__ msg1,
                               const float* __restrict__ msg2, const float* __restrict__ den,
                               const float* __restrict__ b1, const float* __restrict__ b2,
                               const float* __restrict__ b3,
                               const float* __restrict__ ht,
                               __nv_bfloat16* __restrict__ xhi,
                               __nv_bfloat16* __restrict__ xlo) {
    const int i2 = blockIdx.x * blockDim.x + threadIdx.x;
    if (i2 >= NT * HID / 2) return;
    const int idx = i2 * 2;
    const int n = idx >> 8;
    const int k = idx & 255;
    const int h = k >> 6;
    const float d0 = fmaxf(den[0 * NT * H + n * 4 + h], 1e-16f);
    const float d1 = fmaxf(den[1 * NT * H + n * 4 + h], 1e-16f);
    const float d2 = fmaxf(den[2 * NT * H + n * 4 + h], 1e-16f);
    const float2 m0 = *reinterpret_cast<const float2*>(msg0 + idx);
    const float2 m1 = *reinterpret_cast<const float2*>(msg1 + idx);
    const float2 m2 = *reinterpret_cast<const float2*>(msg2 + idx);
    const float2 hh = *reinterpret_cast<const float2*>(ht + idx);
    const float o1x = m0.x / d0 + b1[k],     o1y = m0.y / d0 + b1[k + 1];
    const float o2x = m1.x / d1 + b2[k],     o2y = m1.y / d1 + b2[k + 1];
    const float o3x = m2.x / d2 + b3[k],     o3y = m2.y / d2 + b3[k + 1];
    float x0 = 0.25f * (o1x + o2x) + 0.5f * o3x + hh.x;
    float x1 = 0.25f * (o1y + o2y) + 0.5f * o3y + hh.y;
    x0 = fmaxf(x0, 0.f);
    x1 = fmaxf(x1, 0.f);
    __nv_bfloat16 h0, h1, l0, l1;
    split1(x0, h0, l0); split1(x1, h1, l1);
    *reinterpret_cast<uint32_t*>(xhi + idx) = pk(h0, h1);
    *reinterpret_cast<uint32_t*>(xlo + idx) = pk(l0, l1);
}

// ---------------- launch ----------------
extern "C" void kernel_launch(void* const* d_in, const int* in_sizes, int n_in,
                              void* d_out, int out_size) {
    const float* x_target = (const float*)d_in[0];
    const float* x_context = (const float*)d_in[1];
    const int*   ei_tt     = (const int*)d_in[2];
    const int*   ei_ct_src = (const int*)d_in[3];
    const int*   ei_ct_dst = (const int*)d_in[4];
    const float* Wt = (const float*)d_in[5];
    const float* bt = (const float*)d_in[6];
    const float* Wc = (const float*)d_in[7];
    const float* bc = (const float*)d_in[8];
    const float* W_s2d  = (const float*)d_in[9];
    const float* as_s2d = (const float*)d_in[10];
    const float* ad_s2d = (const float*)d_in[11];
    const float* b_s2d  = (const float*)d_in[12];
    const float* W_d2s  = (const float*)d_in[13];
    const float* as_d2s = (const float*)d_in[14];
    const float* ad_d2s = (const float*)d_in[15];
    const float* b_d2s  = (const float*)d_in[16];
    const float* W_ct_src = (const float*)d_in[17];
    const float* W_ct_dst = (const float*)d_in[18];
    const float* as_ct  = (const float*)d_in[19];
    const float* ad_ct  = (const float*)d_in[20];
    const float* b_ct   = (const float*)d_in[21];
    const float* W_out  = (const float*)d_in[22];
    const float* b_out  = (const float*)d_in[23];

    float *ht, *p1, *p2, *pd, *ps, *msg0, *msg1, *msg2, *den;
    float *as0, *ad0, *as1, *ad1, *as2, *ad2;
    cudaGetSymbolAddress((void**)&ht,   g_ht);
    cudaGetSymbolAddress((void**)&p1,   g_p1);
    cudaGetSymbolAddress((void**)&p2,   g_p2);
    cudaGetSymbolAddress((void**)&pd,   g_pd);
    cudaGetSymbolAddress((void**)&ps,   g_ps);
    cudaGetSymbolAddress((void**)&msg0, g_msg0);
    cudaGetSymbolAddress((void**)&msg1, g_msg1);
    cudaGetSymbolAddress((void**)&msg2, g_msg2);
    cudaGetSymbolAddress((void**)&den,  g_den);
    cudaGetSymbolAddress((void**)&as0,  g_as0);
    cudaGetSymbolAddress((void**)&ad0,  g_ad0);
    cudaGetSymbolAddress((void**)&as1,  g_as1);
    cudaGetSymbolAddress((void**)&ad1,  g_ad1);
    cudaGetSymbolAddress((void**)&as2,  g_as2);
    cudaGetSymbolAddress((void**)&ad2,  g_ad2);

    __nv_bfloat16 *xt_hi, *xt_lo, *xc_hi, *xc_lo, *ht_hi, *ht_lo, *hc_hi, *hc_lo;
    __nv_bfloat16 *xb_hi, *xb_lo;
    __nv_bfloat16 *wt_hi, *wt_lo, *wc_hi, *wc_lo, *w1_hi, *w1_lo, *w2_hi, *w2_lo;
    __nv_bfloat16 *wd_hi, *wd_lo, *ws_hi, *ws_lo, *wo_hi, *wo_lo;
    cudaGetSymbolAddress((void**)&xt_hi, g_xt_hi); cudaGetSymbolAddress((void**)&xt_lo, g_xt_lo);
    cudaGetSymbolAddress((void**)&xc_hi, g_xc_hi); cudaGetSymbolAddress((void**)&xc_lo, g_xc_lo);
    cudaGetSymbolAddress((void**)&ht_hi, g_ht_hi); cudaGetSymbolAddress((void**)&ht_lo, g_ht_lo);
    cudaGetSymbolAddress((void**)&hc_hi, g_hc_hi); cudaGetSymbolAddress((void**)&hc_lo, g_hc_lo);
    cudaGetSymbolAddress((void**)&xb_hi, g_xb_hi); cudaGetSymbolAddress((void**)&xb_lo, g_xb_lo);
    cudaGetSymbolAddress((void**)&wt_hi, g_wt_hi); cudaGetSymbolAddress((void**)&wt_lo, g_wt_lo);
    cudaGetSymbolAddress((void**)&wc_hi, g_wc_hi); cudaGetSymbolAddress((void**)&wc_lo, g_wc_lo);
    cudaGetSymbolAddress((void**)&w1_hi, g_w1_hi); cudaGetSymbolAddress((void**)&w1_lo, g_w1_lo);
    cudaGetSymbolAddress((void**)&w2_hi, g_w2_hi); cudaGetSymbolAddress((void**)&w2_lo, g_w2_lo);
    cudaGetSymbolAddress((void**)&wd_hi, g_wd_hi); cudaGetSymbolAddress((void**)&wd_lo, g_wd_lo);
    cudaGetSymbolAddress((void**)&ws_hi, g_ws_hi); cudaGetSymbolAddress((void**)&ws_lo, g_ws_lo);
    cudaGetSymbolAddress((void**)&wo_hi, g_wo_hi); cudaGetSymbolAddress((void**)&wo_lo, g_wo_lo);

    // opt-in large dynamic smem (host-side, not captured; idempotent)
    static bool attr_done = false;
    if (!attr_done) {
        cudaFuncSetAttribute(mma_gemm2<true, true, true, true>,
                             cudaFuncAttributeMaxDynamicSharedMemorySize, GEMM_SMEM);
        cudaFuncSetAttribute(mma_gemm2<true, true, false, true>,
                             cudaFuncAttributeMaxDynamicSharedMemorySize, GEMM_SMEM);
        cudaFuncSetAttribute(mma_gemm2<false, false, true, false>,
                             cudaFuncAttributeMaxDynamicSharedMemorySize, GEMM_SMEM);
        cudaFuncSetAttribute(mma_gemm2<true, false, true, false>,
                             cudaFuncAttributeMaxDynamicSharedMemorySize, GEMM_SMEM);
        attr_done = true;
    }

    // zero accumulators
    cudaMemsetAsync(msg0, 0, sizeof(float) * NT * HID, 0);
    cudaMemsetAsync(msg1, 0, sizeof(float) * NT * HID, 0);
    cudaMemsetAsync(msg2, 0, sizeof(float) * NT * HID, 0);
    cudaMemsetAsync(den,  0, sizeof(float) * 3 * NT * H, 0);

    // ---- conversions ----
    split_kernel<<<(NT * FT / 4 + 255) / 256, 256>>>(x_target, xt_hi, xt_lo, NT * FT / 4);
    split_kernel<<<(NC * FC / 4 + 255) / 256, 256>>>(x_context, xc_hi, xc_lo, NC * FC / 4);
    splitT_kernel<<<(FT * HID + 255) / 256, 256>>>(Wt, wt_hi, wt_lo, FT, HID);
    splitT_kernel<<<(FC * HID + 255) / 256, 256>>>(Wc, wc_hi, wc_lo, FC, HID);
    splitT_kernel<<<(HID * HID + 255) / 256, 256>>>(W_s2d, w1_hi, w1_lo, HID, HID);
    splitT_kernel<<<(HID * HID + 255) / 256, 256>>>(W_d2s, w2_hi, w2_lo, HID, HID);
    splitT_kernel<<<(HID * HID + 255) / 256, 256>>>(W_ct_dst, wd_hi, wd_lo, HID, HID);
    splitT_kernel<<<(HID * HID + 255) / 256, 256>>>(W_ct_src, ws_hi, ws_lo, HID, HID);
    splitT_kernel<<<(HID * HID + 255) / 256, 256>>>(W_out, wo_hi, wo_lo, HID, HID);

    const dim3 blk(512);
    const dim3 g_nt(HID / 128, (NT + 127) / 128);
    const dim3 g_nc(HID / 128, (NC + 127) / 128);

    // pretransform + relu (ht: f32 + bf16; hc: bf16 only)
    mma_gemm2<true, true, true, true><<<g_nt, blk, GEMM_SMEM>>>(
        xt_hi, xt_lo, wt_hi, wt_lo, bt, ht, ht_hi, ht_lo, NT, HID, FT);
    mma_gemm2<true, true, false, true><<<g_nc, blk, GEMM_SMEM>>>(
        xc_hi, xc_lo, wc_hi, wc_lo, bc, nullptr, hc_hi, hc_lo, NC, HID, FC);

    // projections (f32 only)
    mma_gemm2<false, false, true, false><<<g_nt, blk, GEMM_SMEM>>>(
        ht_hi, ht_lo, w1_hi, w1_lo, nullptr, p1, nullptr, nullptr, NT, HID, HID);
    mma_gemm2<false, false, true, false><<<g_nt, blk, GEMM_SMEM>>>(
        ht_hi, ht_lo, w2_hi, w2_lo, nullptr, p2, nullptr, nullptr, NT, HID, HID);
    mma_gemm2<false, false, true, false><<<g_nt, blk, GEMM_SMEM>>>(
        ht_hi, ht_lo, wd_hi, wd_lo, nullptr, pd, nullptr, nullptr, NT, HID, HID);
    mma_gemm2<false, false, true, false><<<g_nc, blk, GEMM_SMEM>>>(
        hc_hi, hc_lo, ws_hi, ws_lo, nullptr, ps, nullptr, nullptr, NC, HID, HID);

    const int* tt_src = ei_tt;
    const int* tt_dst = ei_tt + E_TT;

    // ---- attention logits ----
    const int aw_nt = NT * H * 32;
    const int aw_nc = NC * H * 32;
    alpha01_kernel<<<(aw_nt + 255) / 256, 256>>>(p1, p2, as_s2d, ad_s2d, as_d2s, ad_d2s,
                                                 as0, ad0, as1, ad1);
    alpha_kernel<<<(aw_nc + 255) / 256, 256>>>(ps, as_ct, as2, NC);
    alpha_kernel<<<(aw_nt + 255) / 256, 256>>>(pd, ad_ct, ad2, NT);

    // ---- edge passes (no segment-max; softmax is shift-invariant, logits O(1)) ----
    const int ett_total = E_TT + NT;
    edge01_kernel<<<(ett_total * 32 + 255) / 256, 256>>>(
        tt_src, tt_dst, as0, ad0, as1, ad1, p1, p2,
        den, den + NT * H, msg0, msg1);
    edge2_kernel<<<(E_CT * 32 + 255) / 256, 256>>>(
        ei_ct_src, ei_ct_dst, as2, ad2, ps, den + 2 * NT * H, msg2);

    // ---- combine -> xb (bf16 hi/lo) ----
    combine_kernel<<<(NT * HID / 2 + 255) / 256, 256>>>(
        msg0, msg1, msg2, den, b_s2d, b_d2s, b_ct, ht, xb_hi, xb_lo);

    // ---- final linear ----
    mma_gemm2<true, false, true, false><<<g_nt, blk, GEMM_SMEM>>>(
        xb_hi, xb_lo, wo_hi, wo_lo, b_out, (float*)d_out, nullptr, nullptr, NT, HID, HID);
}

// round 5
// speedup vs baseline: 1.9516x; 1.3034x over previous
#include <cuda_runtime.h>
#include <cuda_bf16.h>
#include <math.h>
#include <stdint.h>

// ---------------- problem constants ----------------
constexpr int NT  = 50000;
constexpr int NC  = 10000;
constexpr int H   = 4;
constexpr int HID = 256;
constexpr int E_TT = 400000;
constexpr int E_CT = 200000;
constexpr int FT = 128;
constexpr int FC = 64;
constexpr int PW = 768;        // p1|p2|pd concat width

// ---------------- device scratch ----------------
__device__ float g_ht[NT * HID];
__device__ float g_p[NT * PW];           // [NT][768]: p1 | p2 | pd
__device__ float g_ps[NC * HID];
__device__ float g_as0[NT * H], g_ad0[NT * H];
__device__ float g_as1[NT * H], g_ad1[NT * H];
__device__ float g_as2[NC * H], g_ad2[NT * H];
// CSR scratch
__device__ int g_cnt[3 * NT];
__device__ int g_cur[3 * NT];
__device__ int g_rowp[3 * (NT + 1)];
__device__ int g_col0[E_TT];
__device__ int g_col1[E_TT];
__device__ int g_col2[E_CT];
// bf16 hi/lo activations
__device__ __nv_bfloat16 g_xt_hi[NT * FT],  g_xt_lo[NT * FT];
__device__ __nv_bfloat16 g_xc_hi[NC * FC],  g_xc_lo[NC * FC];
__device__ __nv_bfloat16 g_ht_hi[NT * HID], g_ht_lo[NT * HID];
__device__ __nv_bfloat16 g_hc_hi[NC * HID], g_hc_lo[NC * HID];
__device__ __nv_bfloat16 g_xb_hi[NT * HID], g_xb_lo[NT * HID];
// bf16 hi/lo transposed weights [N, K]
__device__ __nv_bfloat16 g_wt_hi[HID * FT],  g_wt_lo[HID * FT];
__device__ __nv_bfloat16 g_wc_hi[HID * FC],  g_wc_lo[HID * FC];
__device__ __nv_bfloat16 g_w3_hi[PW * HID],  g_w3_lo[PW * HID];   // s2d|d2s|ct_dst
__device__ __nv_bfloat16 g_ws_hi[HID * HID], g_ws_lo[HID * HID];
__device__ __nv_bfloat16 g_wo_hi[HID * HID], g_wo_lo[HID * HID];

__device__ __forceinline__ uint32_t pk(__nv_bfloat16 a, __nv_bfloat16 b) {
    return (uint32_t)__bfloat16_as_ushort(a) | ((uint32_t)__bfloat16_as_ushort(b) << 16);
}
__device__ __forceinline__ void split1(float v, __nv_bfloat16& h, __nv_bfloat16& l) {
    h = __float2bfloat16(v);
    l = __float2bfloat16(v - __bfloat162float(h));
}

// ---------------- conversion kernels ----------------
__global__ void split_kernel(const float* __restrict__ src,
                             __nv_bfloat16* __restrict__ hi, __nv_bfloat16* __restrict__ lo,
                             int n4) {
    const int i4 = blockIdx.x * blockDim.x + threadIdx.x;
    if (i4 >= n4) return;
    const int i = i4 * 4;
    const float4 v = *reinterpret_cast<const float4*>(src + i);
    __nv_bfloat16 h0, h1, h2, h3, l0, l1, l2, l3;
    split1(v.x, h0, l0); split1(v.y, h1, l1);
    split1(v.z, h2, l2); split1(v.w, h3, l3);
    uint32_t* ph = reinterpret_cast<uint32_t*>(hi + i);
    uint32_t* pl = reinterpret_cast<uint32_t*>(lo + i);
    ph[0] = pk(h0, h1); ph[1] = pk(h2, h3);
    pl[0] = pk(l0, l1); pl[1] = pk(l2, l3);
}

// weight [K, N] fp32 -> hi/lo [(nOff+n), K] bf16 (transposed, row offset)
__global__ void splitT_kernel(const float* __restrict__ W,
                              __nv_bfloat16* __restrict__ hi, __nv_bfloat16* __restrict__ lo,
                              int K, int N, int nOff) {
    const int idx = blockIdx.x * blockDim.x + threadIdx.x;
    if (idx >= K * N) return;
    const int k = idx / N, n = idx % N;
    __nv_bfloat16 h, l;
    split1(W[idx], h, l);
    hi[(size_t)(nOff + n) * K + k] = h;
    lo[(size_t)(nOff + n) * K + k] = l;
}

// ---------------- CSR build ----------------
__global__ void count_kernel(const int* __restrict__ tt_src, const int* __restrict__ tt_dst,
                             const int* __restrict__ ct_dst, int* __restrict__ cnt) {
    const int e = blockIdx.x * blockDim.x + threadIdx.x;
    if (e < E_TT) {
        atomicAdd(&cnt[tt_dst[e]], 1);
        atomicAdd(&cnt[NT + tt_src[e]], 1);
    }
    if (e < E_CT) atomicAdd(&cnt[2 * NT + ct_dst[e]], 1);
}

__global__ void __launch_bounds__(1024) scan3_kernel(
        const int* __restrict__ cnt, int* __restrict__ rowp, int* __restrict__ cur) {
    const int a = blockIdx.x;
    const int* c = cnt + a * NT;
    int* rp = rowp + a * (NT + 1);
    int* cu = cur + a * NT;
    __shared__ int warp_tot[32];
    __shared__ int s_carry;
    const int tid = threadIdx.x;
    const int lane = tid & 31, wid = tid >> 5;
    if (tid == 0) s_carry = 0;
    __syncthreads();
    for (int base = 0; base < NT; base += 1024) {
        const int i = base + tid;
        const int v = (i < NT) ? c[i] : 0;
        int x = v;
#pragma unroll
        for (int o = 1; o < 32; o <<= 1) {
            const int y = __shfl_up_sync(~0u, x, o);
            if (lane >= o) x += y;
        }
        if (lane == 31) warp_tot[wid] = x;
        __syncthreads();
        if (wid == 0) {
            int t = warp_tot[lane];
#pragma unroll
            for (int o = 1; o < 32; o <<= 1) {
                const int y = __shfl_up_sync(~0u, t, o);
                if (lane >= o) t += y;
            }
            warp_tot[lane] = t;
        }
        __syncthreads();
        const int carry = s_carry;
        const int woff = (wid > 0) ? warp_tot[wid - 1] : 0;
        const int excl = carry + woff + (x - v);
        if (i < NT) { rp[i] = excl; cu[i] = excl; }
        __syncthreads();
        if (tid == 0) s_carry = carry + warp_tot[31];
        __syncthreads();
    }
    if (tid == 0) rp[NT] = s_carry;
}

__global__ void scatter_kernel(const int* __restrict__ tt_src, const int* __restrict__ tt_dst,
                               const int* __restrict__ ct_src, const int* __restrict__ ct_dst,
                               int* __restrict__ cur,
                               int* __restrict__ col0, int* __restrict__ col1,
                               int* __restrict__ col2) {
    const int e = blockIdx.x * blockDim.x + threadIdx.x;
    if (e < E_TT) {
        const int s = tt_src[e], d = tt_dst[e];
        col0[atomicAdd(&cur[d], 1)] = s;
        col1[atomicAdd(&cur[NT + s], 1)] = d;
    }
    if (e < E_CT) {
        col2[atomicAdd(&cur[2 * NT + ct_dst[e]], 1)] = ct_src[e];
    }
}

// ================= bf16 double-split tensor-core GEMM =================
constexpr int SA = 40;
constexpr int TILE_ARR = 128 * SA;
constexpr int OFF_AHI = 0;
constexpr int OFF_ALO = TILE_ARR;
constexpr int OFF_BHI = 2 * TILE_ARR;
constexpr int OFF_BLO = 3 * TILE_ARR;
constexpr int BUF_STRIDE = 4 * TILE_ARR;
constexpr int GEMM_SMEM = 2 * BUF_STRIDE * 2;

__device__ __forceinline__ void cp16(__nv_bfloat16* smem, const __nv_bfloat16* gmem) {
    uint32_t sa = (uint32_t)__cvta_generic_to_shared(smem);
    asm volatile("cp.async.ca.shared.global [%0], [%1], 16;" :: "r"(sa), "l"(gmem));
}

__device__ __forceinline__ void mma16816(float* c, const uint32_t* a, const uint32_t* b) {
    asm volatile(
        "mma.sync.aligned.m16n8k16.row.col.f32.bf16.bf16.f32 "
        "{%0,%1,%2,%3}, {%4,%5,%6,%7}, {%8,%9}, {%0,%1,%2,%3};"
        : "+f"(c[0]), "+f"(c[1]), "+f"(c[2]), "+f"(c[3])
        : "r"(a[0]), "r"(a[1]), "r"(a[2]), "r"(a[3]), "r"(b[0]), "r"(b[1]));
}

template <bool BIAS, bool RELU, bool WF32, bool WBF16>
__global__ void __launch_bounds__(512, 1) mma_gemm2(
        const __nv_bfloat16* __restrict__ Ahi, const __nv_bfloat16* __restrict__ Alo,
        const __nv_bfloat16* __restrict__ Bhi, const __nv_bfloat16* __restrict__ Blo,
        const float* __restrict__ bias,
        float* __restrict__ Cf32, __nv_bfloat16* __restrict__ Chi,
        __nv_bfloat16* __restrict__ Clo,
        int M, int N, int K) {
    extern __shared__ __align__(16) char dynsmem[];
    __nv_bfloat16* sm = reinterpret_cast<__nv_bfloat16*>(dynsmem);

    const int tid = threadIdx.x;
    const int bm = blockIdx.y * 128;
    const int bn = blockIdx.x * 128;
    const int wid = tid >> 5;
    const int lane = tid & 31;
    const int wm = wid >> 2;
    const int wn = wid & 3;
    const int g = lane >> 2;
    const int t = lane & 3;

    const int frow = tid >> 2;
    const int fkc  = (tid & 3) * 8;
    int garow = bm + frow; if (garow >= M) garow = M - 1;
    const int gbrow = bn + frow;

    float acc[2][4][4];
#pragma unroll
    for (int mi = 0; mi < 2; mi++)
#pragma unroll
        for (int ni = 0; ni < 4; ni++)
#pragma unroll
            for (int r = 0; r < 4; r++) acc[mi][ni][r] = 0.f;

    const int KT = K >> 5;
    {
        const size_t ao = (size_t)garow * K + fkc;
        const size_t bo = (size_t)gbrow * K + fkc;
        __nv_bfloat16* b0 = sm;
        cp16(b0 + OFF_AHI + frow * SA + fkc, Ahi + ao);
        cp16(b0 + OFF_ALO + frow * SA + fkc, Alo + ao);
        cp16(b0 + OFF_BHI + frow * SA + fkc, Bhi + bo);
        cp16(b0 + OFF_BLO + frow * SA + fkc, Blo + bo);
        asm volatile("cp.async.commit_group;");
    }

    for (int kt = 0; kt < KT; kt++) {
        asm volatile("cp.async.wait_group 0;");
        __syncthreads();
        if (kt + 1 < KT) {
            const int k0 = (kt + 1) << 5;
            const size_t ao = (size_t)garow * K + k0 + fkc;
            const size_t bo = (size_t)gbrow * K + k0 + fkc;
            __nv_bfloat16* nb = sm + ((kt + 1) & 1) * BUF_STRIDE;
            cp16(nb + OFF_AHI + frow * SA + fkc, Ahi + ao);
            cp16(nb + OFF_ALO + frow * SA + fkc, Alo + ao);
            cp16(nb + OFF_BHI + frow * SA + fkc, Bhi + bo);
            cp16(nb + OFF_BLO + frow * SA + fkc, Blo + bo);
            asm volatile("cp.async.commit_group;");
        }
        const __nv_bfloat16* cb = sm + (kt & 1) * BUF_STRIDE;
        const __nv_bfloat16* sAhi = cb + OFF_AHI;
        const __nv_bfloat16* sAlo = cb + OFF_ALO;
        const __nv_bfloat16* sBhi = cb + OFF_BHI;
        const __nv_bfloat16* sBlo = cb + OFF_BLO;

#pragma unroll
        for (int ks = 0; ks < 2; ks++) {
            const int koff = ks * 16 + 2 * t;
            uint32_t bh[4][2], bl[4][2];
#pragma unroll
            for (int ni = 0; ni < 4; ni++) {
                const int nb = wn * 32 + ni * 8 + g;
                bh[ni][0] = *reinterpret_cast<const uint32_t*>(sBhi + nb * SA + koff);
                bh[ni][1] = *reinterpret_cast<const uint32_t*>(sBhi + nb * SA + koff + 8);
                bl[ni][0] = *reinterpret_cast<const uint32_t*>(sBlo + nb * SA + koff);
                bl[ni][1] = *reinterpret_cast<const uint32_t*>(sBlo + nb * SA + koff + 8);
            }
#pragma unroll
            for (int mi = 0; mi < 2; mi++) {
                const int rb = wm * 32 + mi * 16 + g;
                uint32_t ah[4], al[4];
                ah[0] = *reinterpret_cast<const uint32_t*>(sAhi + rb * SA + koff);
                ah[1] = *reinterpret_cast<const uint32_t*>(sAhi + (rb + 8) * SA + koff);
                ah[2] = *reinterpret_cast<const uint32_t*>(sAhi + rb * SA + koff + 8);
                ah[3] = *reinterpret_cast<const uint32_t*>(sAhi + (rb + 8) * SA + koff + 8);
                al[0] = *reinterpret_cast<const uint32_t*>(sAlo + rb * SA + koff);
                al[1] = *reinterpret_cast<const uint32_t*>(sAlo + (rb + 8) * SA + koff);
                al[2] = *reinterpret_cast<const uint32_t*>(sAlo + rb * SA + koff + 8);
                al[3] = *reinterpret_cast<const uint32_t*>(sAlo + (rb + 8) * SA + koff + 8);
#pragma unroll
                for (int ni = 0; ni < 4; ni++) {
                    mma16816(acc[mi][ni], ah, bh[ni]);
                    mma16816(acc[mi][ni], ah, bl[ni]);
                    mma16816(acc[mi][ni], al, bh[ni]);
                }
            }
        }
        __syncthreads();
    }

#pragma unroll
    for (int mi = 0; mi < 2; mi++) {
        const int row0 = bm + wm * 32 + mi * 16 + g;
#pragma unroll
        for (int ni = 0; ni < 4; ni++) {
            const int col = bn + wn * 32 + ni * 8 + 2 * t;
            float c0 = acc[mi][ni][0], c1 = acc[mi][ni][1];
            float c2 = acc[mi][ni][2], c3 = acc[mi][ni][3];
            if (BIAS) {
                const float b0 = bias[col], b1 = bias[col + 1];
                c0 += b0; c1 += b1; c2 += b0; c3 += b1;
            }
            if (RELU) {
                c0 = fmaxf(c0, 0.f); c1 = fmaxf(c1, 0.f);
                c2 = fmaxf(c2, 0.f); c3 = fmaxf(c3, 0.f);
            }
#pragma unroll
            for (int rr = 0; rr < 2; rr++) {
                const int row = row0 + rr * 8;
                if (row >= M) continue;
                const float v0 = rr ? c2 : c0;
                const float v1 = rr ? c3 : c1;
                const size_t off = (size_t)row * N + col;
                if (WF32)
                    *reinterpret_cast<float2*>(Cf32 + off) = make_float2(v0, v1);
                if (WBF16) {
                    __nv_bfloat16 h0, h1, l0, l1;
                    split1(v0, h0, l0); split1(v1, h1, l1);
                    *reinterpret_cast<uint32_t*>(Chi + off) = pk(h0, h1);
                    *reinterpret_cast<uint32_t*>(Clo + off) = pk(l0, l1);
                }
            }
        }
    }
}

// ---------------- alpha kernels ----------------
// generic: p [N, stride] rows, head h slice at h*64
__global__ void alpha_kernel(const float* __restrict__ p, int stride,
                             const float* __restrict__ att,
                             float* __restrict__ out, int N) {
    const int gw = (blockIdx.x * blockDim.x + threadIdx.x) >> 5;
    const int lane = threadIdx.x & 31;
    if (gw >= N * H) return;
    const int n = gw >> 2;
    const int h = gw & 3;
    const float* pr = p + (size_t)n * stride + h * 64;
    const float* at = att + h * 64;
    float s = pr[lane] * at[lane] + pr[lane + 32] * at[lane + 32];
#pragma unroll
    for (int o = 16; o > 0; o >>= 1) s += __shfl_xor_sync(0xffffffffu, s, o);
    if (lane == 0) out[gw] = s;
}

// fused: 5 dots over p1|p2|pd slices of g_p
__global__ void alpha5_kernel(const float* __restrict__ p,
                              const float* __restrict__ a_s0, const float* __restrict__ a_d0,
                              const float* __restrict__ a_s1, const float* __restrict__ a_d1,
                              const float* __restrict__ a_d2,
                              float* __restrict__ as0, float* __restrict__ ad0,
                              float* __restrict__ as1, float* __restrict__ ad1,
                              float* __restrict__ ad2) {
    const int gw = (blockIdx.x * blockDim.x + threadIdx.x) >> 5;
    const int lane = threadIdx.x & 31;
    if (gw >= NT * H) return;
    const int n = gw >> 2;
    const int h = gw & 3;
    const float* r1 = p + (size_t)n * PW + h * 64;
    const float* r2 = r1 + 256;
    const float* r3 = r1 + 512;
    const float x1a = r1[lane], x1b = r1[lane + 32];
    const float x2a = r2[lane], x2b = r2[lane + 32];
    const float x3a = r3[lane], x3b = r3[lane + 32];
    const float* v;
    v = a_s0 + h * 64; float s0 = x1a * v[lane] + x1b * v[lane + 32];
    v = a_d0 + h * 64; float s1 = x1a * v[lane] + x1b * v[lane + 32];
    v = a_s1 + h * 64; float s2 = x2a * v[lane] + x2b * v[lane + 32];
    v = a_d1 + h * 64; float s3 = x2a * v[lane] + x2b * v[lane + 32];
    v = a_d2 + h * 64; float s4 = x3a * v[lane] + x3b * v[lane + 32];
#pragma unroll
    for (int o = 16; o > 0; o >>= 1) {
        s0 += __shfl_xor_sync(0xffffffffu, s0, o);
        s1 += __shfl_xor_sync(0xffffffffu, s1, o);
        s2 += __shfl_xor_sync(0xffffffffu, s2, o);
        s3 += __shfl_xor_sync(0xffffffffu, s3, o);
        s4 += __shfl_xor_sync(0xffffffffu, s4, o);
    }
    if (lane == 0) { as0[gw] = s0; ad0[gw] = s1; as1[gw] = s2; ad1[gw] = s3; ad2[gw] = s4; }
}

// ---------------- fused CSR gather + combine ----------------
// one warp per target node; lane owns k = lane*8 .. lane*8+7 (head = lane>>3)
__global__ void __launch_bounds__(256) gat_gather(
        const int* __restrict__ rowp,
        const int* __restrict__ col0, const int* __restrict__ col1,
        const int* __restrict__ col2,
        const float* __restrict__ as0, const float* __restrict__ ad0,
        const float* __restrict__ as1, const float* __restrict__ ad1,
        const float* __restrict__ as2, const float* __restrict__ ad2,
        const float* __restrict__ p, const float* __restrict__ ps,
        const float* __restrict__ ht,
        const float* __restrict__ b1, const float* __restrict__ b2,
        const float* __restrict__ b3,
        __nv_bfloat16* __restrict__ xhi, __nv_bfloat16* __restrict__ xlo) {
    const int n = (blockIdx.x * blockDim.x + threadIdx.x) >> 5;
    if (n >= NT) return;
    const int lane = threadIdx.x & 31;
    const int h = lane >> 3;
    const int k = lane * 8;

    const int* rp0 = rowp;
    const int* rp1 = rowp + (NT + 1);
    const int* rp2 = rowp + 2 * (NT + 1);

    float xacc[8];
    float acc[8];

    // ---- pass 0: tt src->dst, x = p1, self loop ----
    {
#pragma unroll
        for (int j = 0; j < 8; j++) acc[j] = 0.f;
        float den = 0.f;
        const float adn = ad0[n * 4 + h];
        const int e0 = rp0[n], e1 = rp0[n + 1];
        for (int e = e0; e < e1; e++) {
            const int s = col0[e];
            float a = as0[s * 4 + h] + adn;
            a = a > 0.f ? a : 0.2f * a;
            const float ex = __expf(a);
            den += ex;
            const float4* xr = reinterpret_cast<const float4*>(p + (size_t)s * PW + k);
            const float4 v0 = xr[0], v1 = xr[1];
            acc[0] += ex * v0.x; acc[1] += ex * v0.y; acc[2] += ex * v0.z; acc[3] += ex * v0.w;
            acc[4] += ex * v1.x; acc[5] += ex * v1.y; acc[6] += ex * v1.z; acc[7] += ex * v1.w;
        }
        {   // self loop
            float a = as0[n * 4 + h] + adn;
            a = a > 0.f ? a : 0.2f * a;
            const float ex = __expf(a);
            den += ex;
            const float4* xr = reinterpret_cast<const float4*>(p + (size_t)n * PW + k);
            const float4 v0 = xr[0], v1 = xr[1];
            acc[0] += ex * v0.x; acc[1] += ex * v0.y; acc[2] += ex * v0.z; acc[3] += ex * v0.w;
            acc[4] += ex * v1.x; acc[5] += ex * v1.y; acc[6] += ex * v1.z; acc[7] += ex * v1.w;
        }
        const float r = 0.25f / fmaxf(den, 1e-16f);
#pragma unroll
        for (int j = 0; j < 8; j++) xacc[j] = r * acc[j];
    }

    // ---- pass 1: tt reversed, x = p2 (offset 256), self loop ----
    {
#pragma unroll
        for (int j = 0; j < 8; j++) acc[j] = 0.f;
        float den = 0.f;
        const float adn = ad1[n * 4 + h];
        const int e0 = rp1[n], e1 = rp1[n + 1];
        for (int e = e0; e < e1; e++) {
            const int s = col1[e];
            float a = as1[s * 4 + h] + adn;
            a = a > 0.f ? a : 0.2f * a;
            const float ex = __expf(a);
            den += ex;
            const float4* xr = reinterpret_cast<const float4*>(p + (size_t)s * PW + 256 + k);
            const float4 v0 = xr[0], v1 = xr[1];
            acc[0] += ex * v0.x; acc[1] += ex * v0.y; acc[2] += ex * v0.z; acc[3] += ex * v0.w;
            acc[4] += ex * v1.x; acc[5] += ex * v1.y; acc[6] += ex * v1.z; acc[7] += ex * v1.w;
        }
        {   // self loop
            float a = as1[n * 4 + h] + adn;
            a = a > 0.f ? a : 0.2f * a;
            const float ex = __expf(a);
            den += ex;
            const float4* xr = reinterpret_cast<const float4*>(p + (size_t)n * PW + 256 + k);
            const float4 v0 = xr[0], v1 = xr[1];
            acc[0] += ex * v0.x; acc[1] += ex * v0.y; acc[2] += ex * v0.z; acc[3] += ex * v0.w;
            acc[4] += ex * v1.x; acc[5] += ex * v1.y; acc[6] += ex * v1.z; acc[7] += ex * v1.w;
        }
        const float r = 0.25f / fmaxf(den, 1e-16f);
#pragma unroll
        for (int j = 0; j < 8; j++) xacc[j] += r * acc[j];
    }

    // ---- pass 2: context->target, x = ps, no self loop ----
    {
#pragma unroll
        for (int j = 0; j < 8; j++) acc[j] = 0.f;
        float den = 0.f;
        const float adn = ad2[n * 4 + h];
        const int e0 = rp2[n], e1 = rp2[n + 1];
        for (int e = e0; e < e1; e++) {
            const int s = col2[e];
            float a = as2[s * 4 + h] + adn;
            a = a > 0.f ? a : 0.2f * a;
            const float ex = __expf(a);
            den += ex;
            const float4* xr = reinterpret_cast<const float4*>(ps + (size_t)s * HID + k);
            const float4 v0 = xr[0], v1 = xr[1];
            acc[0] += ex * v0.x; acc[1] += ex * v0.y; acc[2] += ex * v0.z; acc[3] += ex * v0.w;
            acc[4] += ex * v1.x; acc[5] += ex * v1.y; acc[6] += ex * v1.z; acc[7] += ex * v1.w;
        }
        const float r = 0.5f / fmaxf(den, 1e-16f);
#pragma unroll
        for (int j = 0; j < 8; j++) xacc[j] += r * acc[j];
    }

    // ---- biases + skip + relu + bf16 split ----
    const float4 b1a = *reinterpret_cast<const float4*>(b1 + k);
    const float4 b1b = *reinterpret_cast<const float4*>(b1 + k + 4);
    const float4 b2a = *reinterpret_cast<const float4*>(b2 + k);
    const float4 b2b = *reinterpret_cast<const float4*>(b2 + k + 4);
    const float4 b3a = *reinterpret_cast<const float4*>(b3 + k);
    const float4 b3b = *reinterpret_cast<const float4*>(b3 + k + 4);
    const float4 h0 = *reinterpret_cast<const float4*>(ht + (size_t)n * HID + k);
    const float4 h1 = *reinterpret_cast<const float4*>(ht + (size_t)n * HID + k + 4);
    float xv[8];
    xv[0] = xacc[0] + 0.25f * (b1a.x + b2a.x) + 0.5f * b3a.x + h0.x;
    xv[1] = xacc[1] + 0.25f * (b1a.y + b2a.y) + 0.5f * b3a.y + h0.y;
    xv[2] = xacc[2] + 0.25f * (b1a.z + b2a.z) + 0.5f * b3a.z + h0.z;
    xv[3] = xacc[3] + 0.25f * (b1a.w + b2a.w) + 0.5f * b3a.w + h0.w;
    xv[4] = xacc[4] + 0.25f * (b1b.x + b2b.x) + 0.5f * b3b.x + h1.x;
    xv[5] = xacc[5] + 0.25f * (b1b.y + b2b.y) + 0.5f * b3b.y + h1.y;
    xv[6] = xacc[6] + 0.25f * (b1b.z + b2b.z) + 0.5f * b3b.z + h1.z;
    xv[7] = xacc[7] + 0.25f * (b1b.w + b2b.w) + 0.5f * b3b.w + h1.w;
    uint4 uhi, ulo;
    __nv_bfloat16 hh, ll;
    uint32_t* uh = reinterpret_cast<uint32_t*>(&uhi);
    uint32_t* ul = reinterpret_cast<uint32_t*>(&ulo);
#pragma unroll
    for (int j = 0; j < 4; j++) {
        const float a = fmaxf(xv[2 * j], 0.f);
        const float b = fmaxf(xv[2 * j + 1], 0.f);
        __nv_bfloat16 ha, la, hb, lb;
        split1(a, ha, la); split1(b, hb, lb);
        uh[j] = pk(ha, hb);
        ul[j] = pk(la, lb);
        (void)hh; (void)ll;
    }
    *reinterpret_cast<uint4*>(xhi + (size_t)n * HID + k) = uhi;
    *reinterpret_cast<uint4*>(xlo + (size_t)n * HID + k) = ulo;
}

// ---------------- launch ----------------
extern "C" void kernel_launch(void* const* d_in, const int* in_sizes, int n_in,
                              void* d_out, int out_size) {
    const float* x_target = (const float*)d_in[0];
    const float* x_context = (const float*)d_in[1];
    const int*   ei_tt     = (const int*)d_in[2];
    const int*   ei_ct_src = (const int*)d_in[3];
    const int*   ei_ct_dst = (const int*)d_in[4];
    const float* Wt = (const float*)d_in[5];
    const float* bt = (const float*)d_in[6];
    const float* Wc = (const float*)d_in[7];
    const float* bc = (const float*)d_in[8];
    const float* W_s2d  = (const float*)d_in[9];
    const float* as_s2d = (const float*)d_in[10];
    const float* ad_s2d = (const float*)d_in[11];
    const float* b_s2d  = (const float*)d_in[12];
    const float* W_d2s  = (const float*)d_in[13];
    const float* as_d2s = (const float*)d_in[14];
    const float* ad_d2s = (const float*)d_in[15];
    const float* b_d2s  = (const float*)d_in[16];
    const float* W_ct_src = (const float*)d_in[17];
    const float* W_ct_dst = (const float*)d_in[18];
    const float* as_ct  = (const float*)d_in[19];
    const float* ad_ct  = (const float*)d_in[20];
    const float* b_ct   = (const float*)d_in[21];
    const float* W_out  = (const float*)d_in[22];
    const float* b_out  = (const float*)d_in[23];

    float *ht, *p, *ps, *as0, *ad0, *as1, *ad1, *as2, *ad2;
    cudaGetSymbolAddress((void**)&ht,  g_ht);
    cudaGetSymbolAddress((void**)&p,   g_p);
    cudaGetSymbolAddress((void**)&ps,  g_ps);
    cudaGetSymbolAddress((void**)&as0, g_as0);
    cudaGetSymbolAddress((void**)&ad0, g_ad0);
    cudaGetSymbolAddress((void**)&as1, g_as1);
    cudaGetSymbolAddress((void**)&ad1, g_ad1);
    cudaGetSymbolAddress((void**)&as2, g_as2);
    cudaGetSymbolAddress((void**)&ad2, g_ad2);

    int *cnt, *cur, *rowp, *col0, *col1, *col2;
    cudaGetSymbolAddress((void**)&cnt,  g_cnt);
    cudaGetSymbolAddress((void**)&cur,  g_cur);
    cudaGetSymbolAddress((void**)&rowp, g_rowp);
    cudaGetSymbolAddress((void**)&col0, g_col0);
    cudaGetSymbolAddress((void**)&col1, g_col1);
    cudaGetSymbolAddress((void**)&col2, g_col2);

    __nv_bfloat16 *xt_hi, *xt_lo, *xc_hi, *xc_lo, *ht_hi, *ht_lo, *hc_hi, *hc_lo;
    __nv_bfloat16 *xb_hi, *xb_lo;
    __nv_bfloat16 *wt_hi, *wt_lo, *wc_hi, *wc_lo, *w3_hi, *w3_lo;
    __nv_bfloat16 *ws_hi, *ws_lo, *wo_hi, *wo_lo;
    cudaGetSymbolAddress((void**)&xt_hi, g_xt_hi); cudaGetSymbolAddress((void**)&xt_lo, g_xt_lo);
    cudaGetSymbolAddress((void**)&xc_hi, g_xc_hi); cudaGetSymbolAddress((void**)&xc_lo, g_xc_lo);
    cudaGetSymbolAddress((void**)&ht_hi, g_ht_hi); cudaGetSymbolAddress((void**)&ht_lo, g_ht_lo);
    cudaGetSymbolAddress((void**)&hc_hi, g_hc_hi); cudaGetSymbolAddress((void**)&hc_lo, g_hc_lo);
    cudaGetSymbolAddress((void**)&xb_hi, g_xb_hi); cudaGetSymbolAddress((void**)&xb_lo, g_xb_lo);
    cudaGetSymbolAddress((void**)&wt_hi, g_wt_hi); cudaGetSymbolAddress((void**)&wt_lo, g_wt_lo);
    cudaGetSymbolAddress((void**)&wc_hi, g_wc_hi); cudaGetSymbolAddress((void**)&wc_lo, g_wc_lo);
    cudaGetSymbolAddress((void**)&w3_hi, g_w3_hi); cudaGetSymbolAddress((void**)&w3_lo, g_w3_lo);
    cudaGetSymbolAddress((void**)&ws_hi, g_ws_hi); cudaGetSymbolAddress((void**)&ws_lo, g_ws_lo);
    cudaGetSymbolAddress((void**)&wo_hi, g_wo_hi); cudaGetSymbolAddress((void**)&wo_lo, g_wo_lo);

    static bool attr_done = false;
    if (!attr_done) {
        cudaFuncSetAttribute(mma_gemm2<true, true, true, true>,
                             cudaFuncAttributeMaxDynamicSharedMemorySize, GEMM_SMEM);
        cudaFuncSetAttribute(mma_gemm2<true, true, false, true>,
                             cudaFuncAttributeMaxDynamicSharedMemorySize, GEMM_SMEM);
        cudaFuncSetAttribute(mma_gemm2<false, false, true, false>,
                             cudaFuncAttributeMaxDynamicSharedMemorySize, GEMM_SMEM);
        cudaFuncSetAttribute(mma_gemm2<true, false, true, false>,
                             cudaFuncAttributeMaxDynamicSharedMemorySize, GEMM_SMEM);
        attr_done = true;
    }

    const int* tt_src = ei_tt;
    const int* tt_dst = ei_tt + E_TT;

    // ---- CSR build ----
    cudaMemsetAsync(cnt, 0, sizeof(int) * 3 * NT, 0);
    count_kernel<<<(E_TT + 255) / 256, 256>>>(tt_src, tt_dst, ei_ct_dst, cnt);
    scan3_kernel<<<3, 1024>>>(cnt, rowp, cur);
    scatter_kernel<<<(E_TT + 255) / 256, 256>>>(tt_src, tt_dst, ei_ct_src, ei_ct_dst,
                                                cur, col0, col1, col2);

    // ---- conversions ----
    split_kernel<<<(NT * FT / 4 + 255) / 256, 256>>>(x_target, xt_hi, xt_lo, NT * FT / 4);
    split_kernel<<<(NC * FC / 4 + 255) / 256, 256>>>(x_context, xc_hi, xc_lo, NC * FC / 4);
    splitT_kernel<<<(FT * HID + 255) / 256, 256>>>(Wt, wt_hi, wt_lo, FT, HID, 0);
    splitT_kernel<<<(FC * HID + 255) / 256, 256>>>(Wc, wc_hi, wc_lo, FC, HID, 0);
    splitT_kernel<<<(HID * HID + 255) / 256, 256>>>(W_s2d,   w3_hi, w3_lo, HID, HID, 0);
    splitT_kernel<<<(HID * HID + 255) / 256, 256>>>(W_d2s,   w3_hi, w3_lo, HID, HID, 256);
    splitT_kernel<<<(HID * HID + 255) / 256, 256>>>(W_ct_dst, w3_hi, w3_lo, HID, HID, 512);
    splitT_kernel<<<(HID * HID + 255) / 256, 256>>>(W_ct_src, ws_hi, ws_lo, HID, HID, 0);
    splitT_kernel<<<(HID * HID + 255) / 256, 256>>>(W_out,   wo_hi, wo_lo, HID, HID, 0);

    const dim3 blk(512);
    const dim3 g_ht_g(HID / 128, (NT + 127) / 128);
    const dim3 g_hc_g(HID / 128, (NC + 127) / 128);
    const dim3 g_p_g(PW / 128, (NT + 127) / 128);

    // pretransform + relu
    mma_gemm2<true, true, true, true><<<g_ht_g, blk, GEMM_SMEM>>>(
        xt_hi, xt_lo, wt_hi, wt_lo, bt, ht, ht_hi, ht_lo, NT, HID, FT);
    mma_gemm2<true, true, false, true><<<g_hc_g, blk, GEMM_SMEM>>>(
        xc_hi, xc_lo, wc_hi, wc_lo, bc, nullptr, hc_hi, hc_lo, NC, HID, FC);

    // fused projections: p = ht @ [W_s2d | W_d2s | W_ct_dst]
    mma_gemm2<false, false, true, false><<<g_p_g, blk, GEMM_SMEM>>>(
        ht_hi, ht_lo, w3_hi, w3_lo, nullptr, p, nullptr, nullptr, NT, PW, HID);
    mma_gemm2<false, false, true, false><<<g_hc_g, blk, GEMM_SMEM>>>(
        hc_hi, hc_lo, ws_hi, ws_lo, nullptr, ps, nullptr, nullptr, NC, HID, HID);

    // ---- attention logits ----
    alpha5_kernel<<<(NT * H * 32 + 255) / 256, 256>>>(
        p, as_s2d, ad_s2d, as_d2s, ad_d2s, ad_ct, as0, ad0, as1, ad1, ad2);
    alpha_kernel<<<(NC * H * 32 + 255) / 256, 256>>>(ps, HID, as_ct, as2, NC);

    // ---- fused gather + combine ----
    gat_gather<<<(NT * 32 + 255) / 256, 256>>>(
        rowp, col0, col1, col2, as0, ad0, as1, ad1, as2, ad2,
        p, ps, ht, b_s2d, b_d2s, b_ct, xb_hi, xb_lo);

    // ---- final linear ----
    mma_gemm2<true, false, true, false><<<g_ht_g, blk, GEMM_SMEM>>>(
        xb_hi, xb_lo, wo_hi, wo_lo, b_out, (float*)d_out, nullptr, nullptr, NT, HID, HID);
}

// round 7
// speedup vs baseline: 1.9820x; 1.0156x over previous
#include <cuda_runtime.h>
#include <cuda_bf16.h>
#include <cuda_fp16.h>
#include <math.h>
#include <stdint.h>

// ---------------- problem constants ----------------
constexpr int NT  = 50000;
constexpr int NC  = 10000;
constexpr int H   = 4;
constexpr int HID = 256;
constexpr int E_TT = 400000;
constexpr int E_CT = 200000;
constexpr int FT = 128;
constexpr int FC = 64;
constexpr int PW = 768;        // p1|p2|pd concat width

// ---------------- device scratch ----------------
__device__ float g_ht[NT * HID];
__device__ float g_p[NT * PW];           // fp32 p for alpha logits
__device__ float g_ps[NC * HID];
__device__ __half g_p16[NT * PW];        // fp16 p for gather
__device__ __half g_ps16[NC * HID];
__device__ float g_as0[NT * H], g_ad0[NT * H];
__device__ float g_as1[NT * H], g_ad1[NT * H];
__device__ float g_as2[NC * H], g_ad2[NT * H];
// CSR scratch
__device__ int g_cnt[3 * NT];
__device__ int g_cur[3 * NT];
__device__ int g_rowp[3 * (NT + 1)];
__device__ int g_col0[E_TT];
__device__ int g_col1[E_TT];
__device__ int g_col2[E_CT];
// bf16 hi/lo activations
__device__ __nv_bfloat16 g_xt_hi[NT * FT],  g_xt_lo[NT * FT];
__device__ __nv_bfloat16 g_xc_hi[NC * FC],  g_xc_lo[NC * FC];
__device__ __nv_bfloat16 g_ht_hi[NT * HID], g_ht_lo[NT * HID];
__device__ __nv_bfloat16 g_hc_hi[NC * HID], g_hc_lo[NC * HID];
__device__ __nv_bfloat16 g_xb_hi[NT * HID], g_xb_lo[NT * HID];
// bf16 hi/lo transposed weights [N, K]
__device__ __nv_bfloat16 g_wt_hi[HID * FT],  g_wt_lo[HID * FT];
__device__ __nv_bfloat16 g_wc_hi[HID * FC],  g_wc_lo[HID * FC];
__device__ __nv_bfloat16 g_w3_hi[PW * HID],  g_w3_lo[PW * HID];   // s2d|d2s|ct_dst
__device__ __nv_bfloat16 g_ws_hi[HID * HID], g_ws_lo[HID * HID];
__device__ __nv_bfloat16 g_wo_hi[HID * HID], g_wo_lo[HID * HID];

__device__ __forceinline__ uint32_t pk(__nv_bfloat16 a, __nv_bfloat16 b) {
    return (uint32_t)__bfloat16_as_ushort(a) | ((uint32_t)__bfloat16_as_ushort(b) << 16);
}
__device__ __forceinline__ void split1(float v, __nv_bfloat16& h, __nv_bfloat16& l) {
    h = __float2bfloat16(v);
    l = __float2bfloat16(v - __bfloat162float(h));
}

// ---------------- conversion kernels ----------------
__global__ void split_kernel(const float* __restrict__ src,
                             __nv_bfloat16* __restrict__ hi, __nv_bfloat16* __restrict__ lo,
                             int n4) {
    const int i4 = blockIdx.x * blockDim.x + threadIdx.x;
    if (i4 >= n4) return;
    const int i = i4 * 4;
    const float4 v = *reinterpret_cast<const float4*>(src + i);
    __nv_bfloat16 h0, h1, h2, h3, l0, l1, l2, l3;
    split1(v.x, h0, l0); split1(v.y, h1, l1);
    split1(v.z, h2, l2); split1(v.w, h3, l3);
    uint32_t* ph = reinterpret_cast<uint32_t*>(hi + i);
    uint32_t* pl = reinterpret_cast<uint32_t*>(lo + i);
    ph[0] = pk(h0, h1); ph[1] = pk(h2, h3);
    pl[0] = pk(l0, l1); pl[1] = pk(l2, l3);
}

__global__ void splitT_kernel(const float* __restrict__ W,
                              __nv_bfloat16* __restrict__ hi, __nv_bfloat16* __restrict__ lo,
                              int K, int N, int nOff) {
    const int idx = blockIdx.x * blockDim.x + threadIdx.x;
    if (idx >= K * N) return;
    const int k = idx / N, n = idx % N;
    __nv_bfloat16 h, l;
    split1(W[idx], h, l);
    hi[(size_t)(nOff + n) * K + k] = h;
    lo[(size_t)(nOff + n) * K + k] = l;
}

// ---------------- CSR build ----------------
__global__ void count_kernel(const int* __restrict__ tt_src, const int* __restrict__ tt_dst,
                             const int* __restrict__ ct_dst, int* __restrict__ cnt) {
    const int e = blockIdx.x * blockDim.x + threadIdx.x;
    if (e < E_TT) {
        atomicAdd(&cnt[tt_dst[e]], 1);
        atomicAdd(&cnt[NT + tt_src[e]], 1);
    }
    if (e < E_CT) atomicAdd(&cnt[2 * NT + ct_dst[e]], 1);
}

__global__ void __launch_bounds__(1024) scan3_kernel(
        const int* __restrict__ cnt, int* __restrict__ rowp, int* __restrict__ cur) {
    const int a = blockIdx.x;
    const int* c = cnt + a * NT;
    int* rp = rowp + a * (NT + 1);
    int* cu = cur + a * NT;
    __shared__ int warp_tot[32];
    __shared__ int s_carry;
    const int tid = threadIdx.x;
    const int lane = tid & 31, wid = tid >> 5;
    if (tid == 0) s_carry = 0;
    __syncthreads();
    for (int base = 0; base < NT; base += 1024) {
        const int i = base + tid;
        const int v = (i < NT) ? c[i] : 0;
        int x = v;
#pragma unroll
        for (int o = 1; o < 32; o <<= 1) {
            const int y = __shfl_up_sync(~0u, x, o);
            if (lane >= o) x += y;
        }
        if (lane == 31) warp_tot[wid] = x;
        __syncthreads();
        if (wid == 0) {
            int t = warp_tot[lane];
#pragma unroll
            for (int o = 1; o < 32; o <<= 1) {
                const int y = __shfl_up_sync(~0u, t, o);
                if (lane >= o) t += y;
            }
            warp_tot[lane] = t;
        }
        __syncthreads();
        const int carry = s_carry;
        const int woff = (wid > 0) ? warp_tot[wid - 1] : 0;
        const int excl = carry + woff + (x - v);
        if (i < NT) { rp[i] = excl; cu[i] = excl; }
        __syncthreads();
        if (tid == 0) s_carry = carry + warp_tot[31];
        __syncthreads();
    }
    if (tid == 0) rp[NT] = s_carry;
}

__global__ void scatter_kernel(const int* __restrict__ tt_src, const int* __restrict__ tt_dst,
                               const int* __restrict__ ct_src, const int* __restrict__ ct_dst,
                               int* __restrict__ cur,
                               int* __restrict__ col0, int* __restrict__ col1,
                               int* __restrict__ col2) {
    const int e = blockIdx.x * blockDim.x + threadIdx.x;
    if (e < E_TT) {
        const int s = tt_src[e], d = tt_dst[e];
        col0[atomicAdd(&cur[d], 1)] = s;
        col1[atomicAdd(&cur[NT + s], 1)] = d;
    }
    if (e < E_CT) {
        col2[atomicAdd(&cur[2 * NT + ct_dst[e]], 1)] = ct_src[e];
    }
}

// ================= bf16 double-split tensor-core GEMM =================
constexpr int SA = 40;
constexpr int TILE_ARR = 128 * SA;
constexpr int OFF_AHI = 0;
constexpr int OFF_ALO = TILE_ARR;
constexpr int OFF_BHI = 2 * TILE_ARR;
constexpr int OFF_BLO = 3 * TILE_ARR;
constexpr int BUF_STRIDE = 4 * TILE_ARR;
constexpr int GEMM_SMEM = 2 * BUF_STRIDE * 2;

__device__ __forceinline__ void cp16(__nv_bfloat16* smem, const __nv_bfloat16* gmem) {
    uint32_t sa = (uint32_t)__cvta_generic_to_shared(smem);
    asm volatile("cp.async.ca.shared.global [%0], [%1], 16;" :: "r"(sa), "l"(gmem));
}

__device__ __forceinline__ void mma16816(float* c, const uint32_t* a, const uint32_t* b) {
    asm volatile(
        "mma.sync.aligned.m16n8k16.row.col.f32.bf16.bf16.f32 "
        "{%0,%1,%2,%3}, {%4,%5,%6,%7}, {%8,%9}, {%0,%1,%2,%3};"
        : "+f"(c[0]), "+f"(c[1]), "+f"(c[2]), "+f"(c[3])
        : "r"(a[0]), "r"(a[1]), "r"(a[2]), "r"(a[3]), "r"(b[0]), "r"(b[1]));
}

template <bool BIAS, bool RELU, bool WF32, bool WBF16, bool WF16>
__global__ void __launch_bounds__(512, 1) mma_gemm2(
        const __nv_bfloat16* __restrict__ Ahi, const __nv_bfloat16* __restrict__ Alo,
        const __nv_bfloat16* __restrict__ Bhi, const __nv_bfloat16* __restrict__ Blo,
        const float* __restrict__ bias,
        float* __restrict__ Cf32, __nv_bfloat16* __restrict__ Chi,
        __nv_bfloat16* __restrict__ Clo, __half* __restrict__ C16,
        int M, int N, int K) {
    extern __shared__ __align__(16) char dynsmem[];
    __nv_bfloat16* sm = reinterpret_cast<__nv_bfloat16*>(dynsmem);

    const int tid = threadIdx.x;
    const int bm = blockIdx.y * 128;
    const int bn = blockIdx.x * 128;
    const int wid = tid >> 5;
    const int lane = tid & 31;
    const int wm = wid >> 2;
    const int wn = wid & 3;
    const int g = lane >> 2;
    const int t = lane & 3;

    const int frow = tid >> 2;
    const int fkc  = (tid & 3) * 8;
    int garow = bm + frow; if (garow >= M) garow = M - 1;
    const int gbrow = bn + frow;

    float acc[2][4][4];
#pragma unroll
    for (int mi = 0; mi < 2; mi++)
#pragma unroll
        for (int ni = 0; ni < 4; ni++)
#pragma unroll
            for (int r = 0; r < 4; r++) acc[mi][ni][r] = 0.f;

    const int KT = K >> 5;
    {
        const size_t ao = (size_t)garow * K + fkc;
        const size_t bo = (size_t)gbrow * K + fkc;
        __nv_bfloat16* b0 = sm;
        cp16(b0 + OFF_AHI + frow * SA + fkc, Ahi + ao);
        cp16(b0 + OFF_ALO + frow * SA + fkc, Alo + ao);
        cp16(b0 + OFF_BHI + frow * SA + fkc, Bhi + bo);
        cp16(b0 + OFF_BLO + frow * SA + fkc, Blo + bo);
        asm volatile("cp.async.commit_group;");
    }

    for (int kt = 0; kt < KT; kt++) {
        asm volatile("cp.async.wait_group 0;");
        __syncthreads();
        if (kt + 1 < KT) {
            const int k0 = (kt + 1) << 5;
            const size_t ao = (size_t)garow * K + k0 + fkc;
            const size_t bo = (size_t)gbrow * K + k0 + fkc;
            __nv_bfloat16* nb = sm + ((kt + 1) & 1) * BUF_STRIDE;
            cp16(nb + OFF_AHI + frow * SA + fkc, Ahi + ao);
            cp16(nb + OFF_ALO + frow * SA + fkc, Alo + ao);
            cp16(nb + OFF_BHI + frow * SA + fkc, Bhi + bo);
            cp16(nb + OFF_BLO + frow * SA + fkc, Blo + bo);
            asm volatile("cp.async.commit_group;");
        }
        const __nv_bfloat16* cb = sm + (kt & 1) * BUF_STRIDE;
        const __nv_bfloat16* sAhi = cb + OFF_AHI;
        const __nv_bfloat16* sAlo = cb + OFF_ALO;
        const __nv_bfloat16* sBhi = cb + OFF_BHI;
        const __nv_bfloat16* sBlo = cb + OFF_BLO;

#pragma unroll
        for (int ks = 0; ks < 2; ks++) {
            const int koff = ks * 16 + 2 * t;
            uint32_t bh[4][2], bl[4][2];
#pragma unroll
            for (int ni = 0; ni < 4; ni++) {
                const int nb = wn * 32 + ni * 8 + g;
                bh[ni][0] = *reinterpret_cast<const uint32_t*>(sBhi + nb * SA + koff);
                bh[ni][1] = *reinterpret_cast<const uint32_t*>(sBhi + nb * SA + koff + 8);
                bl[ni][0] = *reinterpret_cast<const uint32_t*>(sBlo + nb * SA + koff);
                bl[ni][1] = *reinterpret_cast<const uint32_t*>(sBlo + nb * SA + koff + 8);
            }
#pragma unroll
            for (int mi = 0; mi < 2; mi++) {
                const int rb = wm * 32 + mi * 16 + g;
                uint32_t ah[4], al[4];
                ah[0] = *reinterpret_cast<const uint32_t*>(sAhi + rb * SA + koff);
                ah[1] = *reinterpret_cast<const uint32_t*>(sAhi + (rb + 8) * SA + koff);
                ah[2] = *reinterpret_cast<const uint32_t*>(sAhi + rb * SA + koff + 8);
                ah[3] = *reinterpret_cast<const uint32_t*>(sAhi + (rb + 8) * SA + koff + 8);
                al[0] = *reinterpret_cast<const uint32_t*>(sAlo + rb * SA + koff);
                al[1] = *reinterpret_cast<const uint32_t*>(sAlo + (rb + 8) * SA + koff);
                al[2] = *reinterpret_cast<const uint32_t*>(sAlo + rb * SA + koff + 8);
                al[3] = *reinterpret_cast<const uint32_t*>(sAlo + (rb + 8) * SA + koff + 8);
#pragma unroll
                for (int ni = 0; ni < 4; ni++) {
                    mma16816(acc[mi][ni], ah, bh[ni]);
                    mma16816(acc[mi][ni], ah, bl[ni]);
                    mma16816(acc[mi][ni], al, bh[ni]);
                }
            }
        }
        __syncthreads();
    }

#pragma unroll
    for (int mi = 0; mi < 2; mi++) {
        const int row0 = bm + wm * 32 + mi * 16 + g;
#pragma unroll
        for (int ni = 0; ni < 4; ni++) {
            const int col = bn + wn * 32 + ni * 8 + 2 * t;
            float c0 = acc[mi][ni][0], c1 = acc[mi][ni][1];
            float c2 = acc[mi][ni][2], c3 = acc[mi][ni][3];
            if (BIAS) {
                const float b0 = bias[col], b1 = bias[col + 1];
                c0 += b0; c1 += b1; c2 += b0; c3 += b1;
            }
            if (RELU) {
                c0 = fmaxf(c0, 0.f); c1 = fmaxf(c1, 0.f);
                c2 = fmaxf(c2, 0.f); c3 = fmaxf(c3, 0.f);
            }
#pragma unroll
            for (int rr = 0; rr < 2; rr++) {
                const int row = row0 + rr * 8;
                if (row >= M) continue;
                const float v0 = rr ? c2 : c0;
                const float v1 = rr ? c3 : c1;
                const size_t off = (size_t)row * N + col;
                if (WF32)
                    *reinterpret_cast<float2*>(Cf32 + off) = make_float2(v0, v1);
                if (WBF16) {
                    __nv_bfloat16 h0, h1, l0, l1;
                    split1(v0, h0, l0); split1(v1, h1, l1);
                    *reinterpret_cast<uint32_t*>(Chi + off) = pk(h0, h1);
                    *reinterpret_cast<uint32_t*>(Clo + off) = pk(l0, l1);
                }
                if (WF16) {
                    const __half2 hv = __float22half2_rn(make_float2(v0, v1));
                    *reinterpret_cast<__half2*>(C16 + off) = hv;
                }
            }
        }
    }
}

// ---------------- alpha kernels ----------------
__global__ void alpha_kernel(const float* __restrict__ p, int stride,
                             const float* __restrict__ att,
                             float* __restrict__ out, int N) {
    const int gw = (blockIdx.x * blockDim.x + threadIdx.x) >> 5;
    const int lane = threadIdx.x & 31;
    if (gw >= N * H) return;
    const int n = gw >> 2;
    const int h = gw & 3;
    const float* pr = p + (size_t)n * stride + h * 64;
    const float* at = att + h * 64;
    float s = pr[lane] * at[lane] + pr[lane + 32] * at[lane + 32];
#pragma unroll
    for (int o = 16; o > 0; o >>= 1) s += __shfl_xor_sync(0xffffffffu, s, o);
    if (lane == 0) out[gw] = s;
}

__global__ void alpha5_kernel(const float* __restrict__ p,
                              const float* __restrict__ a_s0, const float* __restrict__ a_d0,
                              const float* __restrict__ a_s1, const float* __restrict__ a_d1,
                              const float* __restrict__ a_d2,
                              float* __restrict__ as0, float* __restrict__ ad0,
                              float* __restrict__ as1, float* __restrict__ ad1,
                              float* __restrict__ ad2) {
    const int gw = (blockIdx.x * blockDim.x + threadIdx.x) >> 5;
    const int lane = threadIdx.x & 31;
    if (gw >= NT * H) return;
    const int n = gw >> 2;
    const int h = gw & 3;
    const float* r1 = p + (size_t)n * PW + h * 64;
    const float* r2 = r1 + 256;
    const float* r3 = r1 + 512;
    const float x1a = r1[lane], x1b = r1[lane + 32];
    const float x2a = r2[lane], x2b = r2[lane + 32];
    const float x3a = r3[lane], x3b = r3[lane + 32];
    const float* v;
    v = a_s0 + h * 64; float s0 = x1a * v[lane] + x1b * v[lane + 32];
    v = a_d0 + h * 64; float s1 = x1a * v[lane] + x1b * v[lane + 32];
    v = a_s1 + h * 64; float s2 = x2a * v[lane] + x2b * v[lane + 32];
    v = a_d1 + h * 64; float s3 = x2a * v[lane] + x2b * v[lane + 32];
    v = a_d2 + h * 64; float s4 = x3a * v[lane] + x3b * v[lane + 32];
#pragma unroll
    for (int o = 16; o > 0; o >>= 1) {
        s0 += __shfl_xor_sync(0xffffffffu, s0, o);
        s1 += __shfl_xor_sync(0xffffffffu, s1, o);
        s2 += __shfl_xor_sync(0xffffffffu, s2, o);
        s3 += __shfl_xor_sync(0xffffffffu, s3, o);
        s4 += __shfl_xor_sync(0xffffffffu, s4, o);
    }
    if (lane == 0) { as0[gw] = s0; ad0[gw] = s1; as1[gw] = s2; ad1[gw] = s3; ad2[gw] = s4; }
}

// ---------------- fused CSR gather + combine (fp16 message reads) ----------
__device__ __forceinline__ void acc8_f16(float* acc, float ex, const __half* row) {
    const uint4 raw = *reinterpret_cast<const uint4*>(row);
    const __half2* hp = reinterpret_cast<const __half2*>(&raw);
    const float2 f0 = __half22float2(hp[0]);
    const float2 f1 = __half22float2(hp[1]);
    const float2 f2 = __half22float2(hp[2]);
    const float2 f3 = __half22float2(hp[3]);
    acc[0] += ex * f0.x; acc[1] += ex * f0.y;
    acc[2] += ex * f1.x; acc[3] += ex * f1.y;
    acc[4] += ex * f2.x; acc[5] += ex * f2.y;
    acc[6] += ex * f3.x; acc[7] += ex * f3.y;
}

__global__ void __launch_bounds__(256) gat_gather(
        const int* __restrict__ rowp,
        const int* __restrict__ col0, const int* __restrict__ col1,
        const int* __restrict__ col2,
        const float* __restrict__ as0, const float* __restrict__ ad0,
        const float* __restrict__ as1, const float* __restrict__ ad1,
        const float* __restrict__ as2, const float* __restrict__ ad2,
        const __half* __restrict__ p16, const __half* __restrict__ ps16,
        const float* __restrict__ ht,
        const float* __restrict__ b1, const float* __restrict__ b2,
        const float* __restrict__ b3,
        __nv_bfloat16* __restrict__ xhi, __nv_bfloat16* __restrict__ xlo) {
    const int n = (blockIdx.x * blockDim.x + threadIdx.x) >> 5;
    if (n >= NT) return;
    const int lane = threadIdx.x & 31;
    const int h = lane >> 3;
    const int k = lane * 8;

    const int* rp0 = rowp;
    const int* rp1 = rowp + (NT + 1);
    const int* rp2 = rowp + 2 * (NT + 1);

    float xacc[8];
    float acc[8];

    // ---- pass 0: tt src->dst, x = p1 slice, self loop ----
    {
#pragma unroll
        for (int j = 0; j < 8; j++) acc[j] = 0.f;
        float den = 0.f;
        const float adn = ad0[n * 4 + h];
        const int e0 = rp0[n], e1 = rp0[n + 1];
        for (int e = e0; e < e1; e++) {
            const int s = col0[e];
            float a = as0[s * 4 + h] + adn;
            a = a > 0.f ? a : 0.2f * a;
            const float ex = __expf(a);
            den += ex;
            acc8_f16(acc, ex, p16 + (size_t)s * PW + k);
        }
        {
            float a = as0[n * 4 + h] + adn;
            a = a > 0.f ? a : 0.2f * a;
            const float ex = __expf(a);
            den += ex;
            acc8_f16(acc, ex, p16 + (size_t)n * PW + k);
        }
        const float r = 0.25f / fmaxf(den, 1e-16f);
#pragma unroll
        for (int j = 0; j < 8; j++) xacc[j] = r * acc[j];
    }

    // ---- pass 1: tt reversed, x = p2 slice (offset 256), self loop ----
    {
#pragma unroll
        for (int j = 0; j < 8; j++) acc[j] = 0.f;
        float den = 0.f;
        const float adn = ad1[n * 4 + h];
        const int e0 = rp1[n], e1 = rp1[n + 1];
        for (int e = e0; e < e1; e++) {
            const int s = col1[e];
            float a = as1[s * 4 + h] + adn;
            a = a > 0.f ? a : 0.2f * a;
            const float ex = __expf(a);
            den += ex;
            acc8_f16(acc, ex, p16 + (size_t)s * PW + 256 + k);
        }
        {
            float a = as1[n * 4 + h] + adn;
            a = a > 0.f ? a : 0.2f * a;
            const float ex = __expf(a);
            den += ex;
            acc8_f16(acc, ex, p16 + (size_t)n * PW + 256 + k);
        }
        const float r = 0.25f / fmaxf(den, 1e-16f);
#pragma unroll
        for (int j = 0; j < 8; j++) xacc[j] += r * acc[j];
    }

    // ---- pass 2: context->target, x = ps, no self loop ----
    {
#pragma unroll
        for (int j = 0; j < 8; j++) acc[j] = 0.f;
        float den = 0.f;
        const float adn = ad2[n * 4 + h];
        const int e0 = rp2[n], e1 = rp2[n + 1];
        for (int e = e0; e < e1; e++) {
            const int s = col2[e];
            float a = as2[s * 4 + h] + adn;
            a = a > 0.f ? a : 0.2f * a;
            const float ex = __expf(a);
            den += ex;
            acc8_f16(acc, ex, ps16 + (size_t)s * HID + k);
        }
        const float r = 0.5f / fmaxf(den, 1e-16f);
#pragma unroll
        for (int j = 0; j < 8; j++) xacc[j] += r * acc[j];
    }

    const float4 b1a = *reinterpret_cast<const float4*>(b1 + k);
    const float4 b1b = *reinterpret_cast<const float4*>(b1 + k + 4);
    const float4 b2a = *reinterpret_cast<const float4*>(b2 + k);
    const float4 b2b = *reinterpret_cast<const float4*>(b2 + k + 4);
    const float4 b3a = *reinterpret_cast<const float4*>(b3 + k);
    const float4 b3b = *reinterpret_cast<const float4*>(b3 + k + 4);
    const float4 h0 = *reinterpret_cast<const float4*>(ht + (size_t)n * HID + k);
    const float4 h1 = *reinterpret_cast<const float4*>(ht + (size_t)n * HID + k + 4);
    float xv[8];
    xv[0] = xacc[0] + 0.25f * (b1a.x + b2a.x) + 0.5f * b3a.x + h0.x;
    xv[1] = xacc[1] + 0.25f * (b1a.y + b2a.y) + 0.5f * b3a.y + h0.y;
    xv[2] = xacc[2] + 0.25f * (b1a.z + b2a.z) + 0.5f * b3a.z + h0.z;
    xv[3] = xacc[3] + 0.25f * (b1a.w + b2a.w) + 0.5f * b3a.w + h0.w;
    xv[4] = xacc[4] + 0.25f * (b1b.x + b2b.x) + 0.5f * b3b.x + h1.x;
    xv[5] = xacc[5] + 0.25f * (b1b.y + b2b.y) + 0.5f * b3b.y + h1.y;
    xv[6] = xacc[6] + 0.25f * (b1b.z + b2b.z) + 0.5f * b3b.z + h1.z;
    xv[7] = xacc[7] + 0.25f * (b1b.w + b2b.w) + 0.5f * b3b.w + h1.w;
    uint4 uhi, ulo;
    uint32_t* uh = reinterpret_cast<uint32_t*>(&uhi);
    uint32_t* ul = reinterpret_cast<uint32_t*>(&ulo);
#pragma unroll
    for (int j = 0; j < 4; j++) {
        const float a = fmaxf(xv[2 * j], 0.f);
        const float b = fmaxf(xv[2 * j + 1], 0.f);
        __nv_bfloat16 ha, la, hb, lb;
        split1(a, ha, la); split1(b, hb, lb);
        uh[j] = pk(ha, hb);
        ul[j] = pk(la, lb);
    }
    *reinterpret_cast<uint4*>(xhi + (size_t)n * HID + k) = uhi;
    *reinterpret_cast<uint4*>(xlo + (size_t)n * HID + k) = ulo;
}

// ---------------- launch ----------------
extern "C" void kernel_launch(void* const* d_in, const int* in_sizes, int n_in,
                              void* d_out, int out_size) {
    const float* x_target = (const float*)d_in[0];
    const float* x_context = (const float*)d_in[1];
    const int*   ei_tt     = (const int*)d_in[2];
    const int*   ei_ct_src = (const int*)d_in[3];
    const int*   ei_ct_dst = (const int*)d_in[4];
    const float* Wt = (const float*)d_in[5];
    const float* bt = (const float*)d_in[6];
    const float* Wc = (const float*)d_in[7];
    const float* bc = (const float*)d_in[8];
    const float* W_s2d  = (const float*)d_in[9];
    const float* as_s2d = (const float*)d_in[10];
    const float* ad_s2d = (const float*)d_in[11];
    const float* b_s2d  = (const float*)d_in[12];
    const float* W_d2s  = (const float*)d_in[13];
    const float* as_d2s = (const float*)d_in[14];
    const float* ad_d2s = (const float*)d_in[15];
    const float* b_d2s  = (const float*)d_in[16];
    const float* W_ct_src = (const float*)d_in[17];
    const float* W_ct_dst = (const float*)d_in[18];
    const float* as_ct  = (const float*)d_in[19];
    const float* ad_ct  = (const float*)d_in[20];
    const float* b_ct   = (const float*)d_in[21];
    const float* W_out  = (const float*)d_in[22];
    const float* b_out  = (const float*)d_in[23];

    float *ht, *p, *ps, *as0, *ad0, *as1, *ad1, *as2, *ad2;
    cudaGetSymbolAddress((void**)&ht,  g_ht);
    cudaGetSymbolAddress((void**)&p,   g_p);
    cudaGetSymbolAddress((void**)&ps,  g_ps);
    cudaGetSymbolAddress((void**)&as0, g_as0);
    cudaGetSymbolAddress((void**)&ad0, g_ad0);
    cudaGetSymbolAddress((void**)&as1, g_as1);
    cudaGetSymbolAddress((void**)&ad1, g_ad1);
    cudaGetSymbolAddress((void**)&as2, g_as2);
    cudaGetSymbolAddress((void**)&ad2, g_ad2);

    __half *p16, *ps16;
    cudaGetSymbolAddress((void**)&p16,  g_p16);
    cudaGetSymbolAddress((void**)&ps16, g_ps16);

    int *cnt, *cur, *rowp, *col0, *col1, *col2;
    cudaGetSymbolAddress((void**)&cnt,  g_cnt);
    cudaGetSymbolAddress((void**)&cur,  g_cur);
    cudaGetSymbolAddress((void**)&rowp, g_rowp);
    cudaGetSymbolAddress((void**)&col0, g_col0);
    cudaGetSymbolAddress((void**)&col1, g_col1);
    cudaGetSymbolAddress((void**)&col2, g_col2);

    __nv_bfloat16 *xt_hi, *xt_lo, *xc_hi, *xc_lo, *ht_hi, *ht_lo, *hc_hi, *hc_lo;
    __nv_bfloat16 *xb_hi, *xb_lo;
    __nv_bfloat16 *wt_hi, *wt_lo, *wc_hi, *wc_lo, *w3_hi, *w3_lo;
    __nv_bfloat16 *ws_hi, *ws_lo, *wo_hi, *wo_lo;
    cudaGetSymbolAddress((void**)&xt_hi, g_xt_hi); cudaGetSymbolAddress((void**)&xt_lo, g_xt_lo);
    cudaGetSymbolAddress((void**)&xc_hi, g_xc_hi); cudaGetSymbolAddress((void**)&xc_lo, g_xc_lo);
    cudaGetSymbolAddress((void**)&ht_hi, g_ht_hi); cudaGetSymbolAddress((void**)&ht_lo, g_ht_lo);
    cudaGetSymbolAddress((void**)&hc_hi, g_hc_hi); cudaGetSymbolAddress((void**)&hc_lo, g_hc_lo);
    cudaGetSymbolAddress((void**)&xb_hi, g_xb_hi); cudaGetSymbolAddress((void**)&xb_lo, g_xb_lo);
    cudaGetSymbolAddress((void**)&wt_hi, g_wt_hi); cudaGetSymbolAddress((void**)&wt_lo, g_wt_lo);
    cudaGetSymbolAddress((void**)&wc_hi, g_wc_hi); cudaGetSymbolAddress((void**)&wc_lo, g_wc_lo);
    cudaGetSymbolAddress((void**)&w3_hi, g_w3_hi); cudaGetSymbolAddress((void**)&w3_lo, g_w3_lo);
    cudaGetSymbolAddress((void**)&ws_hi, g_ws_hi); cudaGetSymbolAddress((void**)&ws_lo, g_ws_lo);
    cudaGetSymbolAddress((void**)&wo_hi, g_wo_hi); cudaGetSymbolAddress((void**)&wo_lo, g_wo_lo);

    static bool attr_done = false;
    if (!attr_done) {
        cudaFuncSetAttribute(mma_gemm2<true, true, true, true, false>,
                             cudaFuncAttributeMaxDynamicSharedMemorySize, GEMM_SMEM);
        cudaFuncSetAttribute(mma_gemm2<true, true, false, true, false>,
                             cudaFuncAttributeMaxDynamicSharedMemorySize, GEMM_SMEM);
        cudaFuncSetAttribute(mma_gemm2<false, false, true, false, true>,
                             cudaFuncAttributeMaxDynamicSharedMemorySize, GEMM_SMEM);
        cudaFuncSetAttribute(mma_gemm2<true, false, true, false, false>,
                             cudaFuncAttributeMaxDynamicSharedMemorySize, GEMM_SMEM);
        attr_done = true;
    }

    const int* tt_src = ei_tt;
    const int* tt_dst = ei_tt + E_TT;

    // ---- CSR build ----
    cudaMemsetAsync(cnt, 0, sizeof(int) * 3 * NT, 0);
    count_kernel<<<(E_TT + 255) / 256, 256>>>(tt_src, tt_dst, ei_ct_dst, cnt);
    scan3_kernel<<<3, 1024>>>(cnt, rowp, cur);
    scatter_kernel<<<(E_TT + 255) / 256, 256>>>(tt_src, tt_dst, ei_ct_src, ei_ct_dst,
                                                cur, col0, col1, col2);

    // ---- conversions ----
    split_kernel<<<(NT * FT / 4 + 255) / 256, 256>>>(x_target, xt_hi, xt_lo, NT * FT / 4);
    split_kernel<<<(NC * FC / 4 + 255) / 256, 256>>>(x_context, xc_hi, xc_lo, NC * FC / 4);
    splitT_kernel<<<(FT * HID + 255) / 256, 256>>>(Wt, wt_hi, wt_lo, FT, HID, 0);
    splitT_kernel<<<(FC * HID + 255) / 256, 256>>>(Wc, wc_hi, wc_lo, FC, HID, 0);
    splitT_kernel<<<(HID * HID + 255) / 256, 256>>>(W_s2d,   w3_hi, w3_lo, HID, HID, 0);
    splitT_kernel<<<(HID * HID + 255) / 256, 256>>>(W_d2s,   w3_hi, w3_lo, HID, HID, 256);
    splitT_kernel<<<(HID * HID + 255) / 256, 256>>>(W_ct_dst, w3_hi, w3_lo, HID, HID, 512);
    splitT_kernel<<<(HID * HID + 255) / 256, 256>>>(W_ct_src, ws_hi, ws_lo, HID, HID, 0);
    splitT_kernel<<<(HID * HID + 255) / 256, 256>>>(W_out,   wo_hi, wo_lo, HID, HID, 0);

    const dim3 blk(512);
    const dim3 g_ht_g(HID / 128, (NT + 127) / 128);
    const dim3 g_hc_g(HID / 128, (NC + 127) / 128);
    const dim3 g_p_g(PW / 128, (NT + 127) / 128);

    // pretransform + relu
    mma_gemm2<true, true, true, true, false><<<g_ht_g, blk, GEMM_SMEM>>>(
        xt_hi, xt_lo, wt_hi, wt_lo, bt, ht, ht_hi, ht_lo, nullptr, NT, HID, FT);
    mma_gemm2<true, true, false, true, false><<<g_hc_g, blk, GEMM_SMEM>>>(
        xc_hi, xc_lo, wc_hi, wc_lo, bc, nullptr, hc_hi, hc_lo, nullptr, NC, HID, FC);

    // fused projections: p = ht @ [W_s2d | W_d2s | W_ct_dst]  (fp32 + fp16)
    mma_gemm2<false, false, true, false, true><<<g_p_g, blk, GEMM_SMEM>>>(
        ht_hi, ht_lo, w3_hi, w3_lo, nullptr, p, nullptr, nullptr, p16, NT, PW, HID);
    mma_gemm2<false, false, true, false, true><<<g_hc_g, blk, GEMM_SMEM>>>(
        hc_hi, hc_lo, ws_hi, ws_lo, nullptr, ps, nullptr, nullptr, ps16, NC, HID, HID);

    // ---- attention logits (fp32 p) ----
    alpha5_kernel<<<(NT * H * 32 + 255) / 256, 256>>>(
        p, as_s2d, ad_s2d, as_d2s, ad_d2s, ad_ct, as0, ad0, as1, ad1, ad2);
    alpha_kernel<<<(NC * H * 32 + 255) / 256, 256>>>(ps, HID, as_ct, as2, NC);

    // ---- fused gather + combine (fp16 message reads) ----
    gat_gather<<<(NT * 32 + 255) / 256, 256>>>(
        rowp, col0, col1, col2, as0, ad0, as1, ad1, as2, ad2,
        p16, ps16, ht, b_s2d, b_d2s, b_ct, xb_hi, xb_lo);

    // ---- final linear ----
    mma_gemm2<true, false, true, false, false><<<g_ht_g, blk, GEMM_SMEM>>>(
        xb_hi, xb_lo, wo_hi, wo_lo, b_out, (float*)d_out, nullptr, nullptr, nullptr,
        NT, HID, HID);
}